// round 2
// baseline (speedup 1.0000x reference)
#include <cuda_runtime.h>

// Problem constants
#define TT   2048
#define CC   768
#define NQKV 2304
#define HH   12
#define DD   64
#define BBATCH 2
#define MTOK 4096   // B*T

// Scratch (allocation-free rule: __device__ globals)
__device__ float g_qkv[MTOK * NQKV];   // [4096, 2304]
__device__ float g_att[MTOK * CC];     // [4096, 768]

// ---------------------------------------------------------------------------
// SGEMM + bias: C[M,N] = A[M,768] @ B[768,N] + bias[N]
// M = 4096 fixed, K = 768 fixed, N passed (2304 or 768), all divisible by 128/8.
// 128x128 block tile, BK=8, 256 threads, 8x8 per-thread microtile.
// ---------------------------------------------------------------------------
__global__ __launch_bounds__(256) void sgemm_bias_kernel(
    const float* __restrict__ A, const float* __restrict__ B,
    const float* __restrict__ bias, float* __restrict__ C, int N)
{
    __shared__ float As[8][128];
    __shared__ float Bs[8][128];

    const int tid = threadIdx.x;
    const int tx  = tid & 15;     // 0..15 (col group)
    const int ty  = tid >> 4;     // 0..15 (row group)
    const int bx  = blockIdx.x;
    const int by  = blockIdx.y;

    // A tile loader mapping: 128 rows x 8 k, one float4 per thread
    const int arow = tid >> 1;            // 0..127
    const int acol = (tid & 1) << 2;      // 0 or 4
    // B tile loader mapping: 8 k-rows x 128 n, one float4 per thread
    const int brow = tid >> 5;            // 0..7
    const int bcol = (tid & 31) << 2;     // 0..124

    const float* Ap = A + (size_t)(by * 128 + arow) * 768 + acol;
    const float* Bp = B + (size_t)brow * N + bx * 128 + bcol;

    float acc[8][8];
    #pragma unroll
    for (int i = 0; i < 8; i++)
        #pragma unroll
        for (int j = 0; j < 8; j++)
            acc[i][j] = 0.0f;

    for (int k0 = 0; k0 < 768; k0 += 8) {
        float4 av = *(const float4*)(Ap + k0);
        As[acol + 0][arow] = av.x;
        As[acol + 1][arow] = av.y;
        As[acol + 2][arow] = av.z;
        As[acol + 3][arow] = av.w;
        *(float4*)&Bs[brow][bcol] = *(const float4*)(Bp + (size_t)k0 * N);
        __syncthreads();

        #pragma unroll
        for (int k = 0; k < 8; k++) {
            float a[8], b[8];
            *(float4*)&a[0] = *(float4*)&As[k][ty * 8];
            *(float4*)&a[4] = *(float4*)&As[k][ty * 8 + 4];
            *(float4*)&b[0] = *(float4*)&Bs[k][tx * 8];
            *(float4*)&b[4] = *(float4*)&Bs[k][tx * 8 + 4];
            #pragma unroll
            for (int i = 0; i < 8; i++)
                #pragma unroll
                for (int j = 0; j < 8; j++)
                    acc[i][j] += a[i] * b[j];
        }
        __syncthreads();
    }

    // Epilogue: add bias, vectorized stores
    const int col0 = bx * 128 + tx * 8;
    float bl[8];
    *(float4*)&bl[0] = *(const float4*)&bias[col0];
    *(float4*)&bl[4] = *(const float4*)&bias[col0 + 4];

    #pragma unroll
    for (int i = 0; i < 8; i++) {
        const int row = by * 128 + ty * 8 + i;
        float4 r0, r1;
        r0.x = acc[i][0] + bl[0];
        r0.y = acc[i][1] + bl[1];
        r0.z = acc[i][2] + bl[2];
        r0.w = acc[i][3] + bl[3];
        r1.x = acc[i][4] + bl[4];
        r1.y = acc[i][5] + bl[5];
        r1.z = acc[i][6] + bl[6];
        r1.w = acc[i][7] + bl[7];
        *(float4*)&C[(size_t)row * N + col0]     = r0;
        *(float4*)&C[(size_t)row * N + col0 + 4] = r1;
    }
}

// ---------------------------------------------------------------------------
// Flash-attention (fp32, causal). One block per (q_tile=64 rows, head, batch).
// Dynamic smem: Qs/Ks/Vs/Ss [64][68] (stride 68 padding) + row broadcast bufs.
// Online softmax; 256 threads as 16x16, each owns a 4x4 micro-tile.
// Softmax is cooperative: each row handled by a 4-thread group (tid>>6 selects
// the quarter of the row), reduced with shfl_xor.
// ---------------------------------------------------------------------------
#define ASTRIDE 68
#define ATTN_SMEM ((4 * 64 * ASTRIDE + 128) * (int)sizeof(float))

__global__ __launch_bounds__(256) void attn_kernel(
    const float* __restrict__ qkv, float* __restrict__ out)
{
    const int qt = blockIdx.x;   // 0..31  q tile
    const int h  = blockIdx.y;   // 0..11  head
    const int b  = blockIdx.z;   // 0..1   batch

    extern __shared__ float sm[];
    float* Qs = sm;
    float* Ks = sm + 64 * ASTRIDE;
    float* Vs = sm + 2 * 64 * ASTRIDE;
    float* Ss = sm + 3 * 64 * ASTRIDE;
    float* rs = sm + 4 * 64 * ASTRIDE;        // per-row rescale factor [64]
    float* rl = sm + 4 * 64 * ASTRIDE + 64;   // per-row sum l_i [64]

    const int tid = threadIdx.x;
    const int tx  = tid & 15;
    const int ty  = tid >> 4;    // 0..15
    const float scale = 0.125f;  // 1/sqrt(64)

    // Cooperative-softmax mapping: row = tid & 63, quarter = tid >> 6 (0..3)
    const int srow  = tid & 63;
    const int squad = tid >> 6;          // which 16-column quarter
    const int lane  = tid & 31;

    // Load Q tile [64 rows x 64 d] (float4)
    for (int idx = tid; idx < 64 * 16; idx += 256) {
        const int r  = idx >> 4;
        const int c4 = (idx & 15) << 2;
        const size_t g = (size_t)(b * TT + qt * 64 + r) * NQKV + h * DD + c4;
        *(float4*)&Qs[r * ASTRIDE + c4] = *(const float4*)&qkv[g];
    }

    float o[4][4];
    #pragma unroll
    for (int i = 0; i < 4; i++)
        #pragma unroll
        for (int j = 0; j < 4; j++)
            o[i][j] = 0.0f;

    // Per-row softmax state, tracked by all 4 threads of the row's group
    // (replicated; kept consistent because they compute identical reductions).
    float m_i = -1e30f;
    float l_i = 0.0f;

    for (int kt = 0; kt <= qt; kt++) {
        // Load K and V tiles [64 keys x 64 d]
        for (int idx = tid; idx < 64 * 16; idx += 256) {
            const int r  = idx >> 4;
            const int c4 = (idx & 15) << 2;
            const size_t g = (size_t)(b * TT + kt * 64 + r) * NQKV + h * DD + c4;
            *(float4*)&Ks[r * ASTRIDE + c4] = *(const float4*)&qkv[g + CC];
            *(float4*)&Vs[r * ASTRIDE + c4] = *(const float4*)&qkv[g + 2 * CC];
        }
        __syncthreads();

        // S = (Q K^T) * scale  (4x4 per thread)
        float s[4][4];
        #pragma unroll
        for (int i = 0; i < 4; i++)
            #pragma unroll
            for (int j = 0; j < 4; j++)
                s[i][j] = 0.0f;

        #pragma unroll 8
        for (int d = 0; d < 64; d++) {
            float a[4], bb[4];
            #pragma unroll
            for (int ii = 0; ii < 4; ii++) a[ii]  = Qs[(ty + ii * 16) * ASTRIDE + d];
            #pragma unroll
            for (int jj = 0; jj < 4; jj++) bb[jj] = Ks[(tx + jj * 16) * ASTRIDE + d];
            #pragma unroll
            for (int ii = 0; ii < 4; ii++)
                #pragma unroll
                for (int jj = 0; jj < 4; jj++)
                    s[ii][jj] += a[ii] * bb[jj];
        }

        // Write S (scaled, masked on diagonal tile)
        #pragma unroll
        for (int ii = 0; ii < 4; ii++) {
            const int i = ty + ii * 16;
            #pragma unroll
            for (int jj = 0; jj < 4; jj++) {
                const int j = tx + jj * 16;
                float v = s[ii][jj] * scale;
                if (kt == qt && j > i) v = -1e30f;
                Ss[i * ASTRIDE + j] = v;
            }
        }
        __syncthreads();

        // Cooperative online softmax: 4 threads per row, 16 cols each.
        // Groups of 4 collaborating threads are lanes {l, l^8, l^16(via other
        // warp? no)} — careful: squad spans tid>>6 i.e. DIFFERENT warps.
        // Instead reduce via smem-free shuffle within warp is impossible across
        // warps, so each thread scans its 16 columns and we combine via smem.
        {
            const int c0 = squad * 16;
            float mx = -1e30f;
            #pragma unroll
            for (int j = 0; j < 16; j++)
                mx = fmaxf(mx, Ss[srow * ASTRIDE + c0 + j]);
            // combine 4 partial maxima through smem (rs reused as scratch)
            // stage 1: each squad writes its partial to rl[row] slots via atomic-free
            // two-phase: use 4 separate banks of scratch
            __shared__ float pmax[4][64];
            __shared__ float psum[4][64];
            pmax[squad][srow] = mx;
            __syncthreads();
            float rmax = fmaxf(fmaxf(pmax[0][srow], pmax[1][srow]),
                               fmaxf(pmax[2][srow], pmax[3][srow]));
            rmax = fmaxf(rmax, m_i);
            float ls = 0.0f;
            #pragma unroll
            for (int j = 0; j < 16; j++) {
                const float p = __expf(Ss[srow * ASTRIDE + c0 + j] - rmax);
                Ss[srow * ASTRIDE + c0 + j] = p;
                ls += p;
            }
            psum[squad][srow] = ls;
            __syncthreads();
            const float rsum = psum[0][srow] + psum[1][srow] +
                               psum[2][srow] + psum[3][srow];
            const float sc = __expf(m_i - rmax);
            l_i = l_i * sc + rsum;
            m_i = rmax;
            if (squad == 0) rs[srow] = sc;
        }
        __syncthreads();

        // Rescale O and accumulate P @ V
        float rsc[4];
        #pragma unroll
        for (int ii = 0; ii < 4; ii++) rsc[ii] = rs[ty + ii * 16];
        #pragma unroll
        for (int ii = 0; ii < 4; ii++)
            #pragma unroll
            for (int jj = 0; jj < 4; jj++)
                o[ii][jj] *= rsc[ii];

        #pragma unroll 8
        for (int k = 0; k < 64; k++) {
            float p[4], v[4];
            #pragma unroll
            for (int ii = 0; ii < 4; ii++) p[ii] = Ss[(ty + ii * 16) * ASTRIDE + k];
            #pragma unroll
            for (int jj = 0; jj < 4; jj++) v[jj] = Vs[k * ASTRIDE + (tx + jj * 16)];
            #pragma unroll
            for (int ii = 0; ii < 4; ii++)
                #pragma unroll
                for (int jj = 0; jj < 4; jj++)
                    o[ii][jj] += p[ii] * v[jj];
        }
        __syncthreads();
    }

    // Final normalization and write-out (squad 0 publishes l_i)
    if (squad == 0) rl[srow] = l_i;
    __syncthreads();

    #pragma unroll
    for (int ii = 0; ii < 4; ii++) {
        const int i = ty + ii * 16;
        const float inv = 1.0f / rl[i];
        const size_t rowbase = (size_t)(b * TT + qt * 64 + i) * CC + h * DD;
        #pragma unroll
        for (int jj = 0; jj < 4; jj++) {
            const int j = tx + jj * 16;
            out[rowbase + j] = o[ii][jj] * inv;
        }
    }
}

// ---------------------------------------------------------------------------
// Launch
// ---------------------------------------------------------------------------
extern "C" void kernel_launch(void* const* d_in, const int* in_sizes, int n_in,
                              void* d_out, int out_size)
{
    const float* x      = (const float*)d_in[0];
    const float* W_attn = (const float*)d_in[1];
    const float* b_attn = (const float*)d_in[2];
    const float* W_proj = (const float*)d_in[3];
    const float* b_proj = (const float*)d_in[4];
    float* out = (float*)d_out;

    float* qkv = nullptr;
    float* att = nullptr;
    cudaGetSymbolAddress((void**)&qkv, g_qkv);
    cudaGetSymbolAddress((void**)&att, g_att);
    cudaFuncSetAttribute(attn_kernel,
                         cudaFuncAttributeMaxDynamicSharedMemorySize, ATTN_SMEM);

    // QKV GEMM: [4096,768] @ [768,2304] + bias
    sgemm_bias_kernel<<<dim3(NQKV / 128, MTOK / 128), 256>>>(x, W_attn, b_attn, qkv, NQKV);
    // Causal attention
    attn_kernel<<<dim3(TT / 64, HH, BBATCH), 256, ATTN_SMEM>>>(qkv, att);
    // Output projection: [4096,768] @ [768,768] + bias -> d_out
    sgemm_bias_kernel<<<dim3(CC / 128, MTOK / 128), 256>>>(att, W_proj, b_proj, out, CC);
}

// round 3
// speedup vs baseline: 2.6745x; 2.6745x over previous
#include <cuda_runtime.h>
#include <cstdint>

// Problem constants
#define TT   2048
#define CC   768
#define NQKV 2304
#define HH   12
#define DD   64
#define BBATCH 2
#define MTOK 4096   // B*T

// Scratch (allocation-free rule: __device__ globals)
__device__ float g_qkv[MTOK * NQKV];   // [4096, 2304]
__device__ float g_att[MTOK * CC];     // [4096, 768]

// ---------------------------------------------------------------------------
// Helpers: tf32 convert + m16n8k8 tf32 MMA
// ---------------------------------------------------------------------------
__device__ __forceinline__ float to_tf32(float x) {
    float y;
    asm("cvt.rna.tf32.f32 %0, %1;" : "=f"(y) : "f"(x));
    return y;
}

__device__ __forceinline__ void mma_tf32(float* d, const float* a, const float* b) {
    asm volatile(
        "mma.sync.aligned.m16n8k8.row.col.f32.tf32.tf32.f32 "
        "{%0,%1,%2,%3}, {%4,%5,%6,%7}, {%8,%9}, {%0,%1,%2,%3};\n"
        : "+f"(d[0]), "+f"(d[1]), "+f"(d[2]), "+f"(d[3])
        : "r"(__float_as_uint(a[0])), "r"(__float_as_uint(a[1])),
          "r"(__float_as_uint(a[2])), "r"(__float_as_uint(a[3])),
          "r"(__float_as_uint(b[0])), "r"(__float_as_uint(b[1])));
}

// ---------------------------------------------------------------------------
// TF32 GEMM + bias: C[M,N] = A[M,768] @ B[768,N] + bias[N]
// Block 128x128, BK=32, 256 threads = 8 warps in 4(M) x 2(N); warp tile 32x64.
// Fragment bank math: A stride 36 -> bank 4r+t (conflict-free),
//                     B stride 136 -> bank 8t+g (conflict-free).
// ---------------------------------------------------------------------------
#define GAS 36
#define GBS 136

__global__ __launch_bounds__(256) void gemm_tf32_kernel(
    const float* __restrict__ A, const float* __restrict__ B,
    const float* __restrict__ bias, float* __restrict__ C, int N)
{
    __shared__ float As[128 * GAS];   // [m][k] 128x32
    __shared__ float Bs[32 * GBS];    // [k][n] 32x128

    const int tid  = threadIdx.x;
    const int lane = tid & 31;
    const int warp = tid >> 5;
    const int wm   = warp >> 1;       // 0..3
    const int wn   = warp & 1;        // 0..1
    const int grp  = lane >> 2;       // 0..7
    const int tig  = lane & 3;        // 0..3
    const int bx   = blockIdx.x;
    const int by   = blockIdx.y;

    // Loader mappings
    const int a_row  = tid >> 3;            // 0..31 (+32*i)
    const int a_col4 = (tid & 7) << 2;      // 0..28
    const int b_krow = tid >> 5;            // 0..7 (+8*i)
    const int b_col4 = (tid & 31) << 2;     // 0..124

    float acc[2][8][4];
    #pragma unroll
    for (int i = 0; i < 2; i++)
        #pragma unroll
        for (int j = 0; j < 8; j++)
            #pragma unroll
            for (int k = 0; k < 4; k++)
                acc[i][j][k] = 0.0f;

    for (int k0 = 0; k0 < 768; k0 += 32) {
        // Load A tile 128x32 (float4, tf32-convert)
        #pragma unroll
        for (int i = 0; i < 4; i++) {
            const int r = a_row + 32 * i;
            float4 v = *(const float4*)&A[(size_t)(by * 128 + r) * 768 + k0 + a_col4];
            v.x = to_tf32(v.x); v.y = to_tf32(v.y);
            v.z = to_tf32(v.z); v.w = to_tf32(v.w);
            *(float4*)&As[r * GAS + a_col4] = v;
        }
        // Load B tile 32x128
        #pragma unroll
        for (int i = 0; i < 4; i++) {
            const int kr = b_krow + 8 * i;
            float4 v = *(const float4*)&B[(size_t)(k0 + kr) * N + bx * 128 + b_col4];
            v.x = to_tf32(v.x); v.y = to_tf32(v.y);
            v.z = to_tf32(v.z); v.w = to_tf32(v.w);
            *(float4*)&Bs[kr * GBS + b_col4] = v;
        }
        __syncthreads();

        #pragma unroll
        for (int ka = 0; ka < 4; ka++) {
            const int kb = ka * 8;
            float afr[2][4];
            #pragma unroll
            for (int ma = 0; ma < 2; ma++) {
                const int r = wm * 32 + ma * 16 + grp;
                afr[ma][0] = As[r * GAS + kb + tig];
                afr[ma][1] = As[(r + 8) * GAS + kb + tig];
                afr[ma][2] = As[r * GAS + kb + tig + 4];
                afr[ma][3] = As[(r + 8) * GAS + kb + tig + 4];
            }
            float bfr[8][2];
            #pragma unroll
            for (int na = 0; na < 8; na++) {
                const int c = wn * 64 + na * 8 + grp;
                bfr[na][0] = Bs[(kb + tig) * GBS + c];
                bfr[na][1] = Bs[(kb + tig + 4) * GBS + c];
            }
            #pragma unroll
            for (int ma = 0; ma < 2; ma++)
                #pragma unroll
                for (int na = 0; na < 8; na++)
                    mma_tf32(acc[ma][na], afr[ma], bfr[na]);
        }
        __syncthreads();
    }

    // Epilogue: bias + store (c0,c1) and (c2,c3) as float2
    #pragma unroll
    for (int ma = 0; ma < 2; ma++) {
        const int row = by * 128 + wm * 32 + ma * 16 + grp;
        #pragma unroll
        for (int na = 0; na < 8; na++) {
            const int col = bx * 128 + wn * 64 + na * 8 + 2 * tig;
            const float2 bv = *(const float2*)&bias[col];
            float2 r0, r1;
            r0.x = acc[ma][na][0] + bv.x;
            r0.y = acc[ma][na][1] + bv.y;
            r1.x = acc[ma][na][2] + bv.x;
            r1.y = acc[ma][na][3] + bv.y;
            *(float2*)&C[(size_t)row * N + col]       = r0;
            *(float2*)&C[(size_t)(row + 8) * N + col] = r1;
        }
    }
}

// ---------------------------------------------------------------------------
// Flash-attention, TF32 tensor-core version.
// Block = (q_tile 64 rows, head, batch); 128 threads = 4 warps.
// Warp w owns rows 16w..16w+15 (one m16 atom). Both QK^T and P@V use
// m16n8k8 tf32 MMA. Online softmax cooperative over 2 squads of 64 threads.
// Q is pre-scaled by 0.125 (exact, power of 2) before tf32 conversion.
// ---------------------------------------------------------------------------
#define FS 68                     // smem row stride (floats); 68 mod 32 = 4
#define ATTN_SMEM (4 * 64 * FS * (int)sizeof(float))

__global__ __launch_bounds__(128) void attn_tf32_kernel(
    const float* __restrict__ qkv, float* __restrict__ out)
{
    const int qt = blockIdx.x;   // 0..31
    const int h  = blockIdx.y;   // 0..11
    const int b  = blockIdx.z;   // 0..1

    extern __shared__ float sm[];
    float* Qs = sm;
    float* Ks = sm + 64 * FS;
    float* Vs = sm + 2 * 64 * FS;
    float* Ss = sm + 3 * 64 * FS;

    __shared__ float rs[64];        // per-row rescale factor
    __shared__ float rl[64];        // per-row final sum
    __shared__ float pmax[2][64];
    __shared__ float psum[2][64];

    const int tid  = threadIdx.x;
    const int lane = tid & 31;
    const int warp = tid >> 5;      // 0..3 -> rows 16*warp..
    const int grp  = lane >> 2;     // 0..7
    const int tig  = lane & 3;      // 0..3

    const int srow  = tid & 63;     // softmax row
    const int squad = tid >> 6;     // 0..1 (32-col half)

    // Load Q tile [64][64], scale by 0.125, tf32-convert
    for (int idx = tid; idx < 64 * 16; idx += 128) {
        const int r  = idx >> 4;
        const int c4 = (idx & 15) << 2;
        const size_t g = (size_t)(b * TT + qt * 64 + r) * NQKV + h * DD + c4;
        float4 v = *(const float4*)&qkv[g];
        v.x = to_tf32(v.x * 0.125f); v.y = to_tf32(v.y * 0.125f);
        v.z = to_tf32(v.z * 0.125f); v.w = to_tf32(v.w * 0.125f);
        *(float4*)&Qs[r * FS + c4] = v;
    }

    float o[8][4];                  // 16 rows x 64 d per warp
    #pragma unroll
    for (int i = 0; i < 8; i++)
        #pragma unroll
        for (int j = 0; j < 4; j++)
            o[i][j] = 0.0f;

    float m_i = -1e30f;
    float l_i = 0.0f;

    for (int kt = 0; kt <= qt; kt++) {
        // Load K and V tiles [64][64], tf32-convert
        for (int idx = tid; idx < 64 * 16; idx += 128) {
            const int r  = idx >> 4;
            const int c4 = (idx & 15) << 2;
            const size_t g = (size_t)(b * TT + kt * 64 + r) * NQKV + h * DD + c4;
            float4 kv = *(const float4*)&qkv[g + CC];
            float4 vv = *(const float4*)&qkv[g + 2 * CC];
            kv.x = to_tf32(kv.x); kv.y = to_tf32(kv.y);
            kv.z = to_tf32(kv.z); kv.w = to_tf32(kv.w);
            vv.x = to_tf32(vv.x); vv.y = to_tf32(vv.y);
            vv.z = to_tf32(vv.z); vv.w = to_tf32(vv.w);
            *(float4*)&Ks[r * FS + c4] = kv;
            *(float4*)&Vs[r * FS + c4] = vv;
        }
        __syncthreads();

        // S = Q K^T (already scaled). 8 key-atoms (n), 8 d-atoms (k).
        float sf[8][4];
        #pragma unroll
        for (int na = 0; na < 8; na++)
            #pragma unroll
            for (int j = 0; j < 4; j++)
                sf[na][j] = 0.0f;

        #pragma unroll
        for (int ka = 0; ka < 8; ka++) {
            const int kb = ka * 8;
            const int r = warp * 16 + grp;
            float afr[4];
            afr[0] = Qs[r * FS + kb + tig];
            afr[1] = Qs[(r + 8) * FS + kb + tig];
            afr[2] = Qs[r * FS + kb + tig + 4];
            afr[3] = Qs[(r + 8) * FS + kb + tig + 4];
            #pragma unroll
            for (int na = 0; na < 8; na++) {
                float bfr[2];
                bfr[0] = Ks[(na * 8 + grp) * FS + kb + tig];
                bfr[1] = Ks[(na * 8 + grp) * FS + kb + tig + 4];
                mma_tf32(sf[na], afr, bfr);
            }
        }

        // Write S to smem with causal mask on the diagonal tile
        {
            const int r0 = warp * 16 + grp;
            #pragma unroll
            for (int na = 0; na < 8; na++) {
                const int c = na * 8 + 2 * tig;
                float v0 = sf[na][0], v1 = sf[na][1];
                float v2 = sf[na][2], v3 = sf[na][3];
                if (kt == qt) {
                    if (c     > r0)     v0 = -1e30f;
                    if (c + 1 > r0)     v1 = -1e30f;
                    if (c     > r0 + 8) v2 = -1e30f;
                    if (c + 1 > r0 + 8) v3 = -1e30f;
                }
                Ss[r0 * FS + c]           = v0;
                Ss[r0 * FS + c + 1]       = v1;
                Ss[(r0 + 8) * FS + c]     = v2;
                Ss[(r0 + 8) * FS + c + 1] = v3;
            }
        }
        __syncthreads();

        // Cooperative online softmax: 2 threads per row, 32 cols each.
        {
            const int c0 = squad * 32;
            float mx = -1e30f;
            #pragma unroll
            for (int j = 0; j < 32; j++)
                mx = fmaxf(mx, Ss[srow * FS + c0 + j]);
            pmax[squad][srow] = mx;
            __syncthreads();
            float rmax = fmaxf(pmax[0][srow], pmax[1][srow]);
            rmax = fmaxf(rmax, m_i);
            float ls = 0.0f;
            #pragma unroll
            for (int j = 0; j < 32; j++) {
                const float p = __expf(Ss[srow * FS + c0 + j] - rmax);
                Ss[srow * FS + c0 + j] = to_tf32(p);
                ls += p;
            }
            psum[squad][srow] = ls;
            __syncthreads();
            const float rsum = psum[0][srow] + psum[1][srow];
            const float sc = __expf(m_i - rmax);
            l_i = l_i * sc + rsum;
            m_i = rmax;
            if (squad == 0) rs[srow] = sc;
        }
        __syncthreads();

        // Rescale O, then O += P @ V
        {
            const float sc0 = rs[warp * 16 + grp];
            const float sc1 = rs[warp * 16 + grp + 8];
            #pragma unroll
            for (int na = 0; na < 8; na++) {
                o[na][0] *= sc0; o[na][1] *= sc0;
                o[na][2] *= sc1; o[na][3] *= sc1;
            }
        }
        #pragma unroll
        for (int ka = 0; ka < 8; ka++) {
            const int kb = ka * 8;
            const int r = warp * 16 + grp;
            float afr[4];
            afr[0] = Ss[r * FS + kb + tig];
            afr[1] = Ss[(r + 8) * FS + kb + tig];
            afr[2] = Ss[r * FS + kb + tig + 4];
            afr[3] = Ss[(r + 8) * FS + kb + tig + 4];
            #pragma unroll
            for (int na = 0; na < 8; na++) {
                float bfr[2];
                bfr[0] = Vs[(kb + tig) * FS + na * 8 + grp];
                bfr[1] = Vs[(kb + tig + 4) * FS + na * 8 + grp];
                mma_tf32(o[na], afr, bfr);
            }
        }
        __syncthreads();
    }

    // Final normalize + store
    if (squad == 0) rl[srow] = l_i;
    __syncthreads();

    {
        const int r0 = warp * 16 + grp;
        const float inv0 = 1.0f / rl[r0];
        const float inv1 = 1.0f / rl[r0 + 8];
        const size_t base0 = (size_t)(b * TT + qt * 64 + r0) * CC + h * DD;
        const size_t base1 = (size_t)(b * TT + qt * 64 + r0 + 8) * CC + h * DD;
        #pragma unroll
        for (int na = 0; na < 8; na++) {
            const int c = na * 8 + 2 * tig;
            float2 w0, w1;
            w0.x = o[na][0] * inv0; w0.y = o[na][1] * inv0;
            w1.x = o[na][2] * inv1; w1.y = o[na][3] * inv1;
            *(float2*)&out[base0 + c] = w0;
            *(float2*)&out[base1 + c] = w1;
        }
    }
}

// ---------------------------------------------------------------------------
// Launch
// ---------------------------------------------------------------------------
extern "C" void kernel_launch(void* const* d_in, const int* in_sizes, int n_in,
                              void* d_out, int out_size)
{
    const float* x      = (const float*)d_in[0];
    const float* W_attn = (const float*)d_in[1];
    const float* b_attn = (const float*)d_in[2];
    const float* W_proj = (const float*)d_in[3];
    const float* b_proj = (const float*)d_in[4];
    float* out = (float*)d_out;

    float* qkv = nullptr;
    float* att = nullptr;
    cudaGetSymbolAddress((void**)&qkv, g_qkv);
    cudaGetSymbolAddress((void**)&att, g_att);
    cudaFuncSetAttribute(attn_tf32_kernel,
                         cudaFuncAttributeMaxDynamicSharedMemorySize, ATTN_SMEM);

    // QKV GEMM: [4096,768] @ [768,2304] + bias
    gemm_tf32_kernel<<<dim3(NQKV / 128, MTOK / 128), 256>>>(x, W_attn, b_attn, qkv, NQKV);
    // Causal attention
    attn_tf32_kernel<<<dim3(TT / 64, HH, BBATCH), 256 / 2, ATTN_SMEM>>>(qkv, att);
    // Output projection: [4096,768] @ [768,768] + bias -> d_out
    gemm_tf32_kernel<<<dim3(CC / 128, MTOK / 128), 256>>>(att, W_proj, b_proj, out, CC);
}

// round 8
// speedup vs baseline: 2.7025x; 1.0105x over previous
#include <cuda_runtime.h>
#include <cstdint>

// Problem constants
#define TT   2048
#define CC   768
#define NQKV 2304
#define HH   12
#define DD   64
#define BBATCH 2
#define MTOK 4096   // B*T

// Scratch (allocation-free rule: __device__ globals)
__device__ float g_qkv[MTOK * NQKV];   // [4096, 2304]
__device__ float g_att[MTOK * CC];     // [4096, 768]

// ---------------------------------------------------------------------------
// Helpers: tf32 convert + m16n8k8 tf32 MMA + cp.async
// ---------------------------------------------------------------------------
__device__ __forceinline__ float to_tf32(float x) {
    float y;
    asm("cvt.rna.tf32.f32 %0, %1;" : "=f"(y) : "f"(x));
    return y;
}

__device__ __forceinline__ void mma_tf32(float* d, const float* a, const float* b) {
    asm volatile(
        "mma.sync.aligned.m16n8k8.row.col.f32.tf32.tf32.f32 "
        "{%0,%1,%2,%3}, {%4,%5,%6,%7}, {%8,%9}, {%0,%1,%2,%3};\n"
        : "+f"(d[0]), "+f"(d[1]), "+f"(d[2]), "+f"(d[3])
        : "r"(__float_as_uint(a[0])), "r"(__float_as_uint(a[1])),
          "r"(__float_as_uint(a[2])), "r"(__float_as_uint(a[3])),
          "r"(__float_as_uint(b[0])), "r"(__float_as_uint(b[1])));
}

__device__ __forceinline__ void cp_async16(void* smem_dst, const void* gmem_src) {
    uint32_t sp = (uint32_t)__cvta_generic_to_shared(smem_dst);
    asm volatile("cp.async.cg.shared.global [%0], [%1], 16;\n"
                 :: "r"(sp), "l"(gmem_src));
}
__device__ __forceinline__ void cp_commit() {
    asm volatile("cp.async.commit_group;\n");
}
__device__ __forceinline__ void cp_wait1() {
    asm volatile("cp.async.wait_group 1;\n");
}

// ---------------------------------------------------------------------------
// TF32 GEMM + bias: C[M,N] = A[M,768] @ B[768,N] + bias[N]
// 128x128 block, BK=32, 256 threads (8 warps, 4Mx2N), warp tile 32x64.
// 2-stage cp.async double buffer; tf32 cvt at fragment load (RNA).
// ---------------------------------------------------------------------------
#define GAS 36
#define GBS 136
#define ASZ (128 * GAS)             // 4608 floats per stage (A)
#define SST (ASZ + 32 * GBS)        // 8960 floats per stage (A+B)
#define GEMM_SMEM (2 * SST * (int)sizeof(float))   // 71680 bytes
#define NKT (768 / 32)              // 24 k-tiles

__global__ __launch_bounds__(256) void gemm_tf32_kernel(
    const float* __restrict__ A, const float* __restrict__ B,
    const float* __restrict__ bias, float* __restrict__ C, int N)
{
    extern __shared__ float smg[];

    const int tid  = threadIdx.x;
    const int lane = tid & 31;
    const int warp = tid >> 5;
    const int wm   = warp >> 1;       // 0..3
    const int wn   = warp & 1;        // 0..1
    const int grp  = lane >> 2;       // 0..7
    const int tig  = lane & 3;        // 0..3
    const int bx   = blockIdx.x;
    const int by   = blockIdx.y;

    const int a_row  = tid >> 3;            // 0..31 (+32*i)
    const int a_col4 = (tid & 7) << 2;      // 0..28
    const int b_krow = tid >> 5;            // 0..7 (+8*i)
    const int b_col4 = (tid & 31) << 2;     // 0..124

    float acc[2][8][4];
    #pragma unroll
    for (int i = 0; i < 2; i++)
        #pragma unroll
        for (int j = 0; j < 8; j++)
            #pragma unroll
            for (int k = 0; k < 4; k++)
                acc[i][j][k] = 0.0f;

    // Async-issue one 128x32 A tile + 32x128 B tile into stage s
    auto issue_tile = [&](int k0, int s) {
        float* dA = smg + s * SST;
        float* dB = smg + s * SST + ASZ;
        #pragma unroll
        for (int i = 0; i < 4; i++) {
            const int r = a_row + 32 * i;
            cp_async16(&dA[r * GAS + a_col4],
                       &A[(size_t)(by * 128 + r) * 768 + k0 + a_col4]);
        }
        #pragma unroll
        for (int i = 0; i < 4; i++) {
            const int kr = b_krow + 8 * i;
            cp_async16(&dB[kr * GBS + b_col4],
                       &B[(size_t)(k0 + kr) * N + bx * 128 + b_col4]);
        }
    };

    issue_tile(0, 0);
    cp_commit();

    for (int t = 0; t < NKT; t++) {
        if (t + 1 < NKT) issue_tile((t + 1) * 32, (t + 1) & 1);
        cp_commit();
        cp_wait1();            // tile t landed
        __syncthreads();

        const float* Asb = smg + (t & 1) * SST;
        const float* Bsb = Asb + ASZ;

        #pragma unroll
        for (int ka = 0; ka < 4; ka++) {
            const int kb = ka * 8;
            float afr[2][4];
            #pragma unroll
            for (int ma = 0; ma < 2; ma++) {
                const int r = wm * 32 + ma * 16 + grp;
                afr[ma][0] = to_tf32(Asb[r * GAS + kb + tig]);
                afr[ma][1] = to_tf32(Asb[(r + 8) * GAS + kb + tig]);
                afr[ma][2] = to_tf32(Asb[r * GAS + kb + tig + 4]);
                afr[ma][3] = to_tf32(Asb[(r + 8) * GAS + kb + tig + 4]);
            }
            float bfr[8][2];
            #pragma unroll
            for (int na = 0; na < 8; na++) {
                const int c = wn * 64 + na * 8 + grp;
                bfr[na][0] = to_tf32(Bsb[(kb + tig) * GBS + c]);
                bfr[na][1] = to_tf32(Bsb[(kb + tig + 4) * GBS + c]);
            }
            #pragma unroll
            for (int ma = 0; ma < 2; ma++)
                #pragma unroll
                for (int na = 0; na < 8; na++)
                    mma_tf32(acc[ma][na], afr[ma], bfr[na]);
        }
        __syncthreads();       // stage (t&1) free for reuse at t+2's issue
    }

    #pragma unroll
    for (int ma = 0; ma < 2; ma++) {
        const int row = by * 128 + wm * 32 + ma * 16 + grp;
        #pragma unroll
        for (int na = 0; na < 8; na++) {
            const int col = bx * 128 + wn * 64 + na * 8 + 2 * tig;
            const float2 bv = *(const float2*)&bias[col];
            float2 r0, r1;
            r0.x = acc[ma][na][0] + bv.x;
            r0.y = acc[ma][na][1] + bv.y;
            r1.x = acc[ma][na][2] + bv.x;
            r1.y = acc[ma][na][3] + bv.y;
            *(float2*)&C[(size_t)row * N + col]       = r0;
            *(float2*)&C[(size_t)(row + 8) * N + col] = r1;
        }
    }
}

// ---------------------------------------------------------------------------
// Flash-attention, TF32 tensor-core, register-resident online softmax.
// Block = (q_tile 128 rows, head, batch); 256 threads = 8 warps.
// ---------------------------------------------------------------------------
#define FS 68
#define ATTN_SMEM ((128 + 64 + 64 + 128) * FS * (int)sizeof(float))

__global__ __launch_bounds__(256, 2) void attn_tf32_kernel(
    const float* __restrict__ qkv, float* __restrict__ out)
{
    const int qi = (int)(gridDim.x - 1) - (int)blockIdx.x;  // heavy tiles first
    const int h  = blockIdx.y;   // 0..11
    const int b  = blockIdx.z;   // 0..1
    const int qbase = qi * 128;

    extern __shared__ float sm[];
    float* Qs = sm;                 // [128][FS]
    float* Ks = sm + 128 * FS;      // [64][FS]
    float* Vs = sm + 192 * FS;      // [64][FS]
    float* Ss = sm + 256 * FS;      // [128][FS]

    const int tid  = threadIdx.x;
    const int lane = tid & 31;
    const int warp = tid >> 5;      // 0..7 -> rows 16*warp..
    const int grp  = lane >> 2;     // 0..7
    const int tig  = lane & 3;      // 0..3

    const int r0 = warp * 16 + grp;     // tile-local row A
    const int r1 = r0 + 8;              // tile-local row B
    const int grow0 = qbase + r0;       // global rows
    const int grow1 = qbase + r1;

    // Load Q tile [128][64], scale by 0.125 (exact), tf32-convert
    for (int idx = tid; idx < 128 * 16; idx += 256) {
        const int r  = idx >> 4;
        const int c4 = (idx & 15) << 2;
        const size_t g = (size_t)(b * TT + qbase + r) * NQKV + h * DD + c4;
        float4 v = *(const float4*)&qkv[g];
        v.x = to_tf32(v.x * 0.125f); v.y = to_tf32(v.y * 0.125f);
        v.z = to_tf32(v.z * 0.125f); v.w = to_tf32(v.w * 0.125f);
        *(float4*)&Qs[r * FS + c4] = v;
    }

    float o[8][4];
    #pragma unroll
    for (int i = 0; i < 8; i++)
        #pragma unroll
        for (int j = 0; j < 4; j++)
            o[i][j] = 0.0f;

    float m0 = -1e30f, m1 = -1e30f;
    float l0 = 0.0f,   l1 = 0.0f;

    const int nkt = 2 * qi + 2;          // k-tiles of 64 keys
    for (int kt = 0; kt < nkt; kt++) {
        // Load K and V tiles [64][64], tf32-convert
        for (int idx = tid; idx < 64 * 16; idx += 256) {
            const int r  = idx >> 4;
            const int c4 = (idx & 15) << 2;
            const size_t g = (size_t)(b * TT + kt * 64 + r) * NQKV + h * DD + c4;
            float4 kv = *(const float4*)&qkv[g + CC];
            float4 vv = *(const float4*)&qkv[g + 2 * CC];
            kv.x = to_tf32(kv.x); kv.y = to_tf32(kv.y);
            kv.z = to_tf32(kv.z); kv.w = to_tf32(kv.w);
            vv.x = to_tf32(vv.x); vv.y = to_tf32(vv.y);
            vv.z = to_tf32(vv.z); vv.w = to_tf32(vv.w);
            *(float4*)&Ks[r * FS + c4] = kv;
            *(float4*)&Vs[r * FS + c4] = vv;
        }
        __syncthreads();

        // S = Q K^T (Q pre-scaled)
        float sf[8][4];
        #pragma unroll
        for (int na = 0; na < 8; na++)
            #pragma unroll
            for (int j = 0; j < 4; j++)
                sf[na][j] = 0.0f;

        #pragma unroll
        for (int ka = 0; ka < 8; ka++) {
            const int kb = ka * 8;
            float afr[4];
            afr[0] = Qs[r0 * FS + kb + tig];
            afr[1] = Qs[r1 * FS + kb + tig];
            afr[2] = Qs[r0 * FS + kb + tig + 4];
            afr[3] = Qs[r1 * FS + kb + tig + 4];
            #pragma unroll
            for (int na = 0; na < 8; na++) {
                float bfr[2];
                bfr[0] = Ks[(na * 8 + grp) * FS + kb + tig];
                bfr[1] = Ks[(na * 8 + grp) * FS + kb + tig + 4];
                mma_tf32(sf[na], afr, bfr);
            }
        }

        // Causal mask (only possible on the last two k-tiles of this q-tile)
        if (kt >= 2 * qi) {
            #pragma unroll
            for (int na = 0; na < 8; na++) {
                const int c = kt * 64 + na * 8 + 2 * tig;
                if (c     > grow0) sf[na][0] = -1e30f;
                if (c + 1 > grow0) sf[na][1] = -1e30f;
                if (c     > grow1) sf[na][2] = -1e30f;
                if (c + 1 > grow1) sf[na][3] = -1e30f;
            }
        }

        // Register online softmax (rows r0, r1): shfl_xor over masks 1,2
        float mx0 = -1e30f, mx1 = -1e30f;
        #pragma unroll
        for (int na = 0; na < 8; na++) {
            mx0 = fmaxf(mx0, fmaxf(sf[na][0], sf[na][1]));
            mx1 = fmaxf(mx1, fmaxf(sf[na][2], sf[na][3]));
        }
        mx0 = fmaxf(mx0, __shfl_xor_sync(0xFFFFFFFFu, mx0, 1));
        mx0 = fmaxf(mx0, __shfl_xor_sync(0xFFFFFFFFu, mx0, 2));
        mx1 = fmaxf(mx1, __shfl_xor_sync(0xFFFFFFFFu, mx1, 1));
        mx1 = fmaxf(mx1, __shfl_xor_sync(0xFFFFFFFFu, mx1, 2));

        const float nm0 = fmaxf(m0, mx0);
        const float nm1 = fmaxf(m1, mx1);
        const float sc0 = __expf(m0 - nm0);
        const float sc1 = __expf(m1 - nm1);
        m0 = nm0; m1 = nm1;

        float s0 = 0.0f, s1 = 0.0f;
        #pragma unroll
        for (int na = 0; na < 8; na++) {
            const float p0 = __expf(sf[na][0] - nm0);
            const float p1 = __expf(sf[na][1] - nm0);
            const float p2 = __expf(sf[na][2] - nm1);
            const float p3 = __expf(sf[na][3] - nm1);
            s0 += p0 + p1;
            s1 += p2 + p3;
            float2 w0, w1;
            w0.x = to_tf32(p0); w0.y = to_tf32(p1);
            w1.x = to_tf32(p2); w1.y = to_tf32(p3);
            *(float2*)&Ss[r0 * FS + na * 8 + 2 * tig] = w0;
            *(float2*)&Ss[r1 * FS + na * 8 + 2 * tig] = w1;
            o[na][0] *= sc0; o[na][1] *= sc0;
            o[na][2] *= sc1; o[na][3] *= sc1;
        }
        s0 += __shfl_xor_sync(0xFFFFFFFFu, s0, 1);
        s0 += __shfl_xor_sync(0xFFFFFFFFu, s0, 2);
        s1 += __shfl_xor_sync(0xFFFFFFFFu, s1, 1);
        s1 += __shfl_xor_sync(0xFFFFFFFFu, s1, 2);
        l0 = l0 * sc0 + s0;
        l1 = l1 * sc1 + s1;

        __syncwarp();   // S rows are warp-private; no block sync needed

        // O += P @ V
        #pragma unroll
        for (int ka = 0; ka < 8; ka++) {
            const int kb = ka * 8;
            float afr[4];
            afr[0] = Ss[r0 * FS + kb + tig];
            afr[1] = Ss[r1 * FS + kb + tig];
            afr[2] = Ss[r0 * FS + kb + tig + 4];
            afr[3] = Ss[r1 * FS + kb + tig + 4];
            #pragma unroll
            for (int na = 0; na < 8; na++) {
                float bfr[2];
                bfr[0] = Vs[(kb + tig) * FS + na * 8 + grp];
                bfr[1] = Vs[(kb + tig + 4) * FS + na * 8 + grp];
                mma_tf32(o[na], afr, bfr);
            }
        }
        __syncthreads();   // protect Ks/Vs before next tile's load
    }

    // Final normalize + store (all state register-resident)
    const float inv0 = 1.0f / l0;
    const float inv1 = 1.0f / l1;
    const size_t base0 = (size_t)(b * TT + grow0) * CC + h * DD;
    const size_t base1 = (size_t)(b * TT + grow1) * CC + h * DD;
    #pragma unroll
    for (int na = 0; na < 8; na++) {
        const int c = na * 8 + 2 * tig;
        float2 w0, w1;
        w0.x = o[na][0] * inv0; w0.y = o[na][1] * inv0;
        w1.x = o[na][2] * inv1; w1.y = o[na][3] * inv1;
        *(float2*)&out[base0 + c] = w0;
        *(float2*)&out[base1 + c] = w1;
    }
}

// ---------------------------------------------------------------------------
// Launch
// ---------------------------------------------------------------------------
extern "C" void kernel_launch(void* const* d_in, const int* in_sizes, int n_in,
                              void* d_out, int out_size)
{
    const float* x      = (const float*)d_in[0];
    const float* W_attn = (const float*)d_in[1];
    const float* b_attn = (const float*)d_in[2];
    const float* W_proj = (const float*)d_in[3];
    const float* b_proj = (const float*)d_in[4];
    float* out = (float*)d_out;

    float* qkv = nullptr;
    float* att = nullptr;
    cudaGetSymbolAddress((void**)&qkv, g_qkv);
    cudaGetSymbolAddress((void**)&att, g_att);
    cudaFuncSetAttribute(gemm_tf32_kernel,
                         cudaFuncAttributeMaxDynamicSharedMemorySize, GEMM_SMEM);
    cudaFuncSetAttribute(attn_tf32_kernel,
                         cudaFuncAttributeMaxDynamicSharedMemorySize, ATTN_SMEM);

    // QKV GEMM: [4096,768] @ [768,2304] + bias
    gemm_tf32_kernel<<<dim3(NQKV / 128, MTOK / 128), 256, GEMM_SMEM>>>(x, W_attn, b_attn, qkv, NQKV);
    // Causal attention (q-tile 128)
    attn_tf32_kernel<<<dim3(TT / 128, HH, BBATCH), 256, ATTN_SMEM>>>(qkv, att);
    // Output projection: [4096,768] @ [768,768] + bias -> d_out
    gemm_tf32_kernel<<<dim3(CC / 128, MTOK / 128), 256, GEMM_SMEM>>>(att, W_proj, b_proj, out, CC);
}

// round 9
// speedup vs baseline: 2.8429x; 1.0519x over previous
#include <cuda_runtime.h>
#include <cstdint>

// Problem constants
#define TT   2048
#define CC   768
#define NQKV 2304
#define HH   12
#define DD   64
#define BBATCH 2
#define MTOK 4096   // B*T

// Scratch (allocation-free rule: __device__ globals)
__device__ float g_qkv[MTOK * NQKV];   // [4096, 2304]
__device__ float g_att[MTOK * CC];     // [4096, 768]

// ---------------------------------------------------------------------------
// Helpers
// ---------------------------------------------------------------------------
__device__ __forceinline__ float to_tf32(float x) {
    float y;
    asm("cvt.rna.tf32.f32 %0, %1;" : "=f"(y) : "f"(x));
    return y;
}

__device__ __forceinline__ float ex2(float x) {
    float y;
    asm("ex2.approx.f32 %0, %1;" : "=f"(y) : "f"(x));
    return y;
}

__device__ __forceinline__ void ldsm_x4(uint32_t& r0, uint32_t& r1,
                                        uint32_t& r2, uint32_t& r3, uint32_t addr) {
    asm volatile("ldmatrix.sync.aligned.m8n8.x4.shared.b16 {%0,%1,%2,%3}, [%4];"
                 : "=r"(r0), "=r"(r1), "=r"(r2), "=r"(r3) : "r"(addr));
}

// d += a*b, tf32 m16n8k8; a,b are raw tf32 bit patterns
__device__ __forceinline__ void mma_tf32_u(float* d, const uint32_t* a, const uint32_t* b) {
    asm volatile(
        "mma.sync.aligned.m16n8k8.row.col.f32.tf32.tf32.f32 "
        "{%0,%1,%2,%3}, {%4,%5,%6,%7}, {%8,%9}, {%0,%1,%2,%3};\n"
        : "+f"(d[0]), "+f"(d[1]), "+f"(d[2]), "+f"(d[3])
        : "r"(a[0]), "r"(a[1]), "r"(a[2]), "r"(a[3]), "r"(b[0]), "r"(b[1]));
}

// ---------------------------------------------------------------------------
// TF32 GEMM + bias: C[M,N] = A[M,768] @ B[768,N] + bias[N]
// 128x128 block, BK=32, 256 threads = 8 warps (2M x 4N), warp tile 64x32.
// A fragments via ldmatrix.x4; B via conflict-free scalar LDS (GBS=136).
// cvt.rna at smem store. Sync loads (cp.async proved neutral in R8).
// ---------------------------------------------------------------------------
#define GAS 36
#define GBS 136

__global__ __launch_bounds__(256) void gemm_tf32_kernel(
    const float* __restrict__ A, const float* __restrict__ B,
    const float* __restrict__ bias, float* __restrict__ C, int N)
{
    __shared__ float As[128 * GAS];
    __shared__ float Bs[32 * GBS];

    const int tid  = threadIdx.x;
    const int lane = tid & 31;
    const int warp = tid >> 5;
    const int wm   = warp >> 2;       // 0..1 (64 rows each)
    const int wn   = warp & 3;        // 0..3 (32 cols each)
    const int grp  = lane >> 2;       // 0..7
    const int tig  = lane & 3;        // 0..3
    const int bx   = blockIdx.x;
    const int by   = blockIdx.y;

    // ldmatrix lane->matrix mapping (A-side): matrices =
    // (rows+0,k 0-3),(rows+8,k 0-3),(rows+0,k 4-7),(rows+8,k 4-7)
    const int part = lane >> 3;                       // 0..3
    const int rsel = (lane & 7) + ((part & 1) << 3);  // row within 16
    const int coff = (part >> 1) << 4;                // 0 or 16 bytes
    const uint32_t as_u32 = (uint32_t)__cvta_generic_to_shared(As);
    const uint32_t a_lm   = as_u32 + (uint32_t)((wm * 64 + rsel) * GAS) * 4u + coff;

    // Loader mappings
    const int a_row  = tid >> 3;            // 0..31 (+32*i)
    const int a_col4 = (tid & 7) << 2;      // 0..28
    const int b_krow = tid >> 5;            // 0..7 (+8*i)
    const int b_col4 = (tid & 31) << 2;     // 0..124

    const int cbase = wn * 32 + grp;

    float acc[4][4][4];
    #pragma unroll
    for (int i = 0; i < 4; i++)
        #pragma unroll
        for (int j = 0; j < 4; j++)
            #pragma unroll
            for (int k = 0; k < 4; k++)
                acc[i][j][k] = 0.0f;

    for (int k0 = 0; k0 < 768; k0 += 32) {
        #pragma unroll
        for (int i = 0; i < 4; i++) {
            const int r = a_row + 32 * i;
            float4 v = *(const float4*)&A[(size_t)(by * 128 + r) * 768 + k0 + a_col4];
            v.x = to_tf32(v.x); v.y = to_tf32(v.y);
            v.z = to_tf32(v.z); v.w = to_tf32(v.w);
            *(float4*)&As[r * GAS + a_col4] = v;
        }
        #pragma unroll
        for (int i = 0; i < 4; i++) {
            const int kr = b_krow + 8 * i;
            float4 v = *(const float4*)&B[(size_t)(k0 + kr) * N + bx * 128 + b_col4];
            v.x = to_tf32(v.x); v.y = to_tf32(v.y);
            v.z = to_tf32(v.z); v.w = to_tf32(v.w);
            *(float4*)&Bs[kr * GBS + b_col4] = v;
        }
        __syncthreads();

        #pragma unroll
        for (int ka = 0; ka < 4; ka++) {
            const int kb = ka * 8;
            uint32_t af[4][4];
            #pragma unroll
            for (int ma = 0; ma < 4; ma++)
                ldsm_x4(af[ma][0], af[ma][1], af[ma][2], af[ma][3],
                        a_lm + (uint32_t)(ma * 16 * GAS) * 4u + (uint32_t)(ka * 32));
            uint32_t bf[4][2];
            #pragma unroll
            for (int na = 0; na < 4; na++) {
                bf[na][0] = __float_as_uint(Bs[(kb + tig) * GBS + cbase + na * 8]);
                bf[na][1] = __float_as_uint(Bs[(kb + tig + 4) * GBS + cbase + na * 8]);
            }
            #pragma unroll
            for (int ma = 0; ma < 4; ma++)
                #pragma unroll
                for (int na = 0; na < 4; na++)
                    mma_tf32_u(acc[ma][na], af[ma], bf[na]);
        }
        __syncthreads();
    }

    #pragma unroll
    for (int ma = 0; ma < 4; ma++) {
        const int row = by * 128 + wm * 64 + ma * 16 + grp;
        #pragma unroll
        for (int na = 0; na < 4; na++) {
            const int col = bx * 128 + wn * 32 + na * 8 + 2 * tig;
            const float2 bv = *(const float2*)&bias[col];
            float2 r0v, r1v;
            r0v.x = acc[ma][na][0] + bv.x;
            r0v.y = acc[ma][na][1] + bv.y;
            r1v.x = acc[ma][na][2] + bv.x;
            r1v.y = acc[ma][na][3] + bv.y;
            *(float2*)&C[(size_t)row * N + col]       = r0v;
            *(float2*)&C[(size_t)(row + 8) * N + col] = r1v;
        }
    }
}

// ---------------------------------------------------------------------------
// Flash-attention, TF32 tensor-core. Q/K/S fragments via ldmatrix; exp2-domain
// softmax (0.125*log2e folded into Q). Register-resident online softmax.
// Block = (q_tile 128, head, batch), 256 threads = 8 warps, 16 rows/warp.
// ---------------------------------------------------------------------------
#define FS 68
#define ATTN_SMEM ((128 + 64 + 64 + 128) * FS * (int)sizeof(float))
#define QSCALE 0.18033688f   // 0.125 * log2(e)

__global__ __launch_bounds__(256, 2) void attn_tf32_kernel(
    const float* __restrict__ qkv, float* __restrict__ out)
{
    const int qi = (int)(gridDim.x - 1) - (int)blockIdx.x;  // heavy tiles first
    const int h  = blockIdx.y;
    const int b  = blockIdx.z;
    const int qbase = qi * 128;

    extern __shared__ float sm[];
    float* Qs = sm;                 // [128][FS]
    float* Ks = sm + 128 * FS;      // [64][FS]
    float* Vs = sm + 192 * FS;      // [64][FS]
    float* Ss = sm + 256 * FS;      // [128][FS]

    const int tid  = threadIdx.x;
    const int lane = tid & 31;
    const int warp = tid >> 5;      // rows 16*warp..16*warp+15
    const int grp  = lane >> 2;
    const int tig  = lane & 3;

    const int row0 = warp * 16 + grp;
    const int row1 = row0 + 8;
    const int grow0 = qbase + row0;
    const int grow1 = qbase + row1;

    // ldmatrix lane mappings
    const int part  = lane >> 3;
    // A-side (Q,S): (r+0,k0-3),(r+8,k0-3),(r+0,k4-7),(r+8,k4-7)
    const int rselA = (lane & 7) + ((part & 1) << 3);
    const int coffA = (part >> 1) << 4;
    // B-side (K): (n+0,k0-3),(n+0,k4-7),(n+8,k0-3),(n+8,k4-7)
    const int rselB = (lane & 7) + ((part >> 1) << 3);
    const int coffB = (part & 1) << 4;

    const uint32_t qs_u32 = (uint32_t)__cvta_generic_to_shared(Qs);
    const uint32_t ks_u32 = (uint32_t)__cvta_generic_to_shared(Ks);
    const uint32_t ss_u32 = (uint32_t)__cvta_generic_to_shared(Ss);
    const uint32_t q_lm = qs_u32 + (uint32_t)((warp * 16 + rselA) * FS) * 4u + coffA;
    const uint32_t s_lm = ss_u32 + (uint32_t)((warp * 16 + rselA) * FS) * 4u + coffA;
    const uint32_t k_lm = ks_u32 + (uint32_t)(rselB * FS) * 4u + coffB;

    // Load Q tile [128][64], scale by 0.125*log2e, tf32-convert
    for (int idx = tid; idx < 128 * 16; idx += 256) {
        const int r  = idx >> 4;
        const int c4 = (idx & 15) << 2;
        const size_t g = (size_t)(b * TT + qbase + r) * NQKV + h * DD + c4;
        float4 v = *(const float4*)&qkv[g];
        v.x = to_tf32(v.x * QSCALE); v.y = to_tf32(v.y * QSCALE);
        v.z = to_tf32(v.z * QSCALE); v.w = to_tf32(v.w * QSCALE);
        *(float4*)&Qs[r * FS + c4] = v;
    }

    float o[8][4];
    #pragma unroll
    for (int i = 0; i < 8; i++)
        #pragma unroll
        for (int j = 0; j < 4; j++)
            o[i][j] = 0.0f;

    float m0 = -1e30f, m1 = -1e30f;
    float l0 = 0.0f,   l1 = 0.0f;

    const int nkt = 2 * qi + 2;
    for (int kt = 0; kt < nkt; kt++) {
        // Load K/V tiles [64][64], tf32-convert
        for (int idx = tid; idx < 64 * 16; idx += 256) {
            const int r  = idx >> 4;
            const int c4 = (idx & 15) << 2;
            const size_t g = (size_t)(b * TT + kt * 64 + r) * NQKV + h * DD + c4;
            float4 kv = *(const float4*)&qkv[g + CC];
            float4 vv = *(const float4*)&qkv[g + 2 * CC];
            kv.x = to_tf32(kv.x); kv.y = to_tf32(kv.y);
            kv.z = to_tf32(kv.z); kv.w = to_tf32(kv.w);
            vv.x = to_tf32(vv.x); vv.y = to_tf32(vv.y);
            vv.z = to_tf32(vv.z); vv.w = to_tf32(vv.w);
            *(float4*)&Ks[r * FS + c4] = kv;
            *(float4*)&Vs[r * FS + c4] = vv;
        }
        __syncthreads();

        // S = Q K^T  (scores already in log2-e domain)
        float sf[8][4];
        #pragma unroll
        for (int na = 0; na < 8; na++)
            #pragma unroll
            for (int j = 0; j < 4; j++)
                sf[na][j] = 0.0f;

        #pragma unroll
        for (int ka = 0; ka < 8; ka++) {
            uint32_t qf[4];
            ldsm_x4(qf[0], qf[1], qf[2], qf[3], q_lm + (uint32_t)(ka * 32));
            uint32_t kf[8][2];
            #pragma unroll
            for (int p = 0; p < 4; p++)
                ldsm_x4(kf[2 * p][0], kf[2 * p][1], kf[2 * p + 1][0], kf[2 * p + 1][1],
                        k_lm + (uint32_t)(p * 16 * FS) * 4u + (uint32_t)(ka * 32));
            #pragma unroll
            for (int na = 0; na < 8; na++)
                mma_tf32_u(sf[na], qf, kf[na]);
        }

        // Causal mask on the last two k-tiles of this q-tile
        if (kt >= 2 * qi) {
            #pragma unroll
            for (int na = 0; na < 8; na++) {
                const int c = kt * 64 + na * 8 + 2 * tig;
                if (c     > grow0) sf[na][0] = -1e30f;
                if (c + 1 > grow0) sf[na][1] = -1e30f;
                if (c     > grow1) sf[na][2] = -1e30f;
                if (c + 1 > grow1) sf[na][3] = -1e30f;
            }
        }

        // Register online softmax (exp2 domain)
        float mx0 = -1e30f, mx1 = -1e30f;
        #pragma unroll
        for (int na = 0; na < 8; na++) {
            mx0 = fmaxf(mx0, fmaxf(sf[na][0], sf[na][1]));
            mx1 = fmaxf(mx1, fmaxf(sf[na][2], sf[na][3]));
        }
        mx0 = fmaxf(mx0, __shfl_xor_sync(0xFFFFFFFFu, mx0, 1));
        mx0 = fmaxf(mx0, __shfl_xor_sync(0xFFFFFFFFu, mx0, 2));
        mx1 = fmaxf(mx1, __shfl_xor_sync(0xFFFFFFFFu, mx1, 1));
        mx1 = fmaxf(mx1, __shfl_xor_sync(0xFFFFFFFFu, mx1, 2));

        const float nm0 = fmaxf(m0, mx0);
        const float nm1 = fmaxf(m1, mx1);
        const float sc0 = ex2(m0 - nm0);
        const float sc1 = ex2(m1 - nm1);
        m0 = nm0; m1 = nm1;

        float s0 = 0.0f, s1 = 0.0f;
        #pragma unroll
        for (int na = 0; na < 8; na++) {
            const float p0 = ex2(sf[na][0] - nm0);
            const float p1 = ex2(sf[na][1] - nm0);
            const float p2 = ex2(sf[na][2] - nm1);
            const float p3 = ex2(sf[na][3] - nm1);
            s0 += p0 + p1;
            s1 += p2 + p3;
            float2 w0, w1;
            w0.x = to_tf32(p0); w0.y = to_tf32(p1);
            w1.x = to_tf32(p2); w1.y = to_tf32(p3);
            *(float2*)&Ss[row0 * FS + na * 8 + 2 * tig] = w0;
            *(float2*)&Ss[row1 * FS + na * 8 + 2 * tig] = w1;
            o[na][0] *= sc0; o[na][1] *= sc0;
            o[na][2] *= sc1; o[na][3] *= sc1;
        }
        s0 += __shfl_xor_sync(0xFFFFFFFFu, s0, 1);
        s0 += __shfl_xor_sync(0xFFFFFFFFu, s0, 2);
        s1 += __shfl_xor_sync(0xFFFFFFFFu, s1, 1);
        s1 += __shfl_xor_sync(0xFFFFFFFFu, s1, 2);
        l0 = l0 * sc0 + s0;
        l1 = l1 * sc1 + s1;

        __syncwarp();   // S rows are warp-private

        // O += P @ V  (S via ldmatrix; V scalar LDS)
        #pragma unroll
        for (int ka = 0; ka < 8; ka++) {
            const int kb = ka * 8;
            uint32_t pf[4];
            ldsm_x4(pf[0], pf[1], pf[2], pf[3], s_lm + (uint32_t)(ka * 32));
            #pragma unroll
            for (int na = 0; na < 8; na++) {
                uint32_t vf[2];
                vf[0] = __float_as_uint(Vs[(kb + tig) * FS + na * 8 + grp]);
                vf[1] = __float_as_uint(Vs[(kb + tig + 4) * FS + na * 8 + grp]);
                mma_tf32_u(o[na], pf, vf);
            }
        }
        __syncthreads();
    }

    // Final normalize + store
    const float inv0 = 1.0f / l0;
    const float inv1 = 1.0f / l1;
    const size_t base0 = (size_t)(b * TT + grow0) * CC + h * DD;
    const size_t base1 = (size_t)(b * TT + grow1) * CC + h * DD;
    #pragma unroll
    for (int na = 0; na < 8; na++) {
        const int c = na * 8 + 2 * tig;
        float2 w0, w1;
        w0.x = o[na][0] * inv0; w0.y = o[na][1] * inv0;
        w1.x = o[na][2] * inv1; w1.y = o[na][3] * inv1;
        *(float2*)&out[base0 + c] = w0;
        *(float2*)&out[base1 + c] = w1;
    }
}

// ---------------------------------------------------------------------------
// Launch
// ---------------------------------------------------------------------------
extern "C" void kernel_launch(void* const* d_in, const int* in_sizes, int n_in,
                              void* d_out, int out_size)
{
    const float* x      = (const float*)d_in[0];
    const float* W_attn = (const float*)d_in[1];
    const float* b_attn = (const float*)d_in[2];
    const float* W_proj = (const float*)d_in[3];
    const float* b_proj = (const float*)d_in[4];
    float* out = (float*)d_out;

    float* qkv = nullptr;
    float* att = nullptr;
    cudaGetSymbolAddress((void**)&qkv, g_qkv);
    cudaGetSymbolAddress((void**)&att, g_att);
    cudaFuncSetAttribute(attn_tf32_kernel,
                         cudaFuncAttributeMaxDynamicSharedMemorySize, ATTN_SMEM);

    gemm_tf32_kernel<<<dim3(NQKV / 128, MTOK / 128), 256>>>(x, W_attn, b_attn, qkv, NQKV);
    attn_tf32_kernel<<<dim3(TT / 128, HH, BBATCH), 256, ATTN_SMEM>>>(qkv, att);
    gemm_tf32_kernel<<<dim3(CC / 128, MTOK / 128), 256>>>(att, W_proj, b_proj, out, CC);
}

// round 12
// speedup vs baseline: 3.3995x; 1.1958x over previous
#include <cuda_runtime.h>
#include <cstdint>

// Problem constants
#define TT   2048
#define CC   768
#define NQKV 2304
#define HH   12
#define DD   64
#define BBATCH 2
#define MTOK 4096   // B*T

// Scratch (allocation-free rule: __device__ globals)
__device__ float g_qkv[MTOK * NQKV];   // [4096, 2304]
__device__ float g_att[MTOK * CC];     // [4096, 768]

// ---------------------------------------------------------------------------
// Helpers
// ---------------------------------------------------------------------------
__device__ __forceinline__ float to_tf32(float x) {
    float y;
    asm("cvt.rna.tf32.f32 %0, %1;" : "=f"(y) : "f"(x));
    return y;
}

__device__ __forceinline__ float ex2(float x) {
    float y;
    asm("ex2.approx.f32 %0, %1;" : "=f"(y) : "f"(x));
    return y;
}

__device__ __forceinline__ void ldsm_x4(uint32_t& r0, uint32_t& r1,
                                        uint32_t& r2, uint32_t& r3, uint32_t addr) {
    asm volatile("ldmatrix.sync.aligned.m8n8.x4.shared.b16 {%0,%1,%2,%3}, [%4];"
                 : "=r"(r0), "=r"(r1), "=r"(r2), "=r"(r3) : "r"(addr));
}

__device__ __forceinline__ void mma_tf32_u(float* d, const uint32_t* a, const uint32_t* b) {
    asm volatile(
        "mma.sync.aligned.m16n8k8.row.col.f32.tf32.tf32.f32 "
        "{%0,%1,%2,%3}, {%4,%5,%6,%7}, {%8,%9}, {%0,%1,%2,%3};\n"
        : "+f"(d[0]), "+f"(d[1]), "+f"(d[2]), "+f"(d[3])
        : "r"(a[0]), "r"(a[1]), "r"(a[2]), "r"(a[3]), "r"(b[0]), "r"(b[1]));
}

// ---------------------------------------------------------------------------
// TF32 GEMM + bias (EXACT R9 version, measured 100.26us / 47.2% tensor = tf32
// HMMA saturation; tcgen05 unavailable: ptxas target rejects it)
// ---------------------------------------------------------------------------
#define GAS 36
#define GBS 136

__global__ __launch_bounds__(256) void gemm_tf32_kernel(
    const float* __restrict__ A, const float* __restrict__ B,
    const float* __restrict__ bias, float* __restrict__ C, int N)
{
    __shared__ float As[128 * GAS];
    __shared__ float Bs[32 * GBS];

    const int tid  = threadIdx.x;
    const int lane = tid & 31;
    const int warp = tid >> 5;
    const int wm   = warp >> 2;
    const int wn   = warp & 3;
    const int grp  = lane >> 2;
    const int tig  = lane & 3;
    const int bx   = blockIdx.x;
    const int by   = blockIdx.y;

    const int part = lane >> 3;
    const int rsel = (lane & 7) + ((part & 1) << 3);
    const int coff = (part >> 1) << 4;
    const uint32_t as_u32 = (uint32_t)__cvta_generic_to_shared(As);
    const uint32_t a_lm   = as_u32 + (uint32_t)((wm * 64 + rsel) * GAS) * 4u + coff;

    const int a_row  = tid >> 3;
    const int a_col4 = (tid & 7) << 2;
    const int b_krow = tid >> 5;
    const int b_col4 = (tid & 31) << 2;

    const int cbase = wn * 32 + grp;

    float acc[4][4][4];
    #pragma unroll
    for (int i = 0; i < 4; i++)
        #pragma unroll
        for (int j = 0; j < 4; j++)
            #pragma unroll
            for (int k = 0; k < 4; k++)
                acc[i][j][k] = 0.0f;

    for (int k0 = 0; k0 < 768; k0 += 32) {
        #pragma unroll
        for (int i = 0; i < 4; i++) {
            const int r = a_row + 32 * i;
            float4 v = *(const float4*)&A[(size_t)(by * 128 + r) * 768 + k0 + a_col4];
            v.x = to_tf32(v.x); v.y = to_tf32(v.y);
            v.z = to_tf32(v.z); v.w = to_tf32(v.w);
            *(float4*)&As[r * GAS + a_col4] = v;
        }
        #pragma unroll
        for (int i = 0; i < 4; i++) {
            const int kr = b_krow + 8 * i;
            float4 v = *(const float4*)&B[(size_t)(k0 + kr) * N + bx * 128 + b_col4];
            v.x = to_tf32(v.x); v.y = to_tf32(v.y);
            v.z = to_tf32(v.z); v.w = to_tf32(v.w);
            *(float4*)&Bs[kr * GBS + b_col4] = v;
        }
        __syncthreads();

        #pragma unroll
        for (int ka = 0; ka < 4; ka++) {
            const int kb = ka * 8;
            uint32_t af[4][4];
            #pragma unroll
            for (int ma = 0; ma < 4; ma++)
                ldsm_x4(af[ma][0], af[ma][1], af[ma][2], af[ma][3],
                        a_lm + (uint32_t)(ma * 16 * GAS) * 4u + (uint32_t)(ka * 32));
            uint32_t bf[4][2];
            #pragma unroll
            for (int na = 0; na < 4; na++) {
                bf[na][0] = __float_as_uint(Bs[(kb + tig) * GBS + cbase + na * 8]);
                bf[na][1] = __float_as_uint(Bs[(kb + tig + 4) * GBS + cbase + na * 8]);
            }
            #pragma unroll
            for (int ma = 0; ma < 4; ma++)
                #pragma unroll
                for (int na = 0; na < 4; na++)
                    mma_tf32_u(acc[ma][na], af[ma], bf[na]);
        }
        __syncthreads();
    }

    #pragma unroll
    for (int ma = 0; ma < 4; ma++) {
        const int row = by * 128 + wm * 64 + ma * 16 + grp;
        #pragma unroll
        for (int na = 0; na < 4; na++) {
            const int col = bx * 128 + wn * 32 + na * 8 + 2 * tig;
            const float2 bv = *(const float2*)&bias[col];
            float2 r0v, r1v;
            r0v.x = acc[ma][na][0] + bv.x;
            r0v.y = acc[ma][na][1] + bv.y;
            r1v.x = acc[ma][na][2] + bv.x;
            r1v.y = acc[ma][na][3] + bv.y;
            *(float2*)&C[(size_t)row * N + col]       = r0v;
            *(float2*)&C[(size_t)(row + 8) * N + col] = r1v;
        }
    }
}

// ---------------------------------------------------------------------------
// Flash-attention, TF32. 4 warps x 32 q-rows (two 16-row m-groups per warp)
// so K/V fragments amortize over 2x q-work; V stride 72 -> conflict-free
// V loads. exp2-domain softmax, ldmatrix Q/K/S fragments, register-resident
// online softmax. Block = (q_tile 128, head, batch), 128 threads.
// ---------------------------------------------------------------------------
#define FS 68
#define VS 72
#define ATTN_SMEM (((128 + 64 + 128) * FS + 64 * VS) * (int)sizeof(float))
#define QSCALE 0.18033688f   // 0.125 * log2(e)

__global__ __launch_bounds__(128, 2) void attn_tf32_kernel(
    const float* __restrict__ qkv, float* __restrict__ out)
{
    const int qi = (int)(gridDim.x - 1) - (int)blockIdx.x;  // heavy tiles first
    const int h  = blockIdx.y;
    const int b  = blockIdx.z;
    const int qbase = qi * 128;

    extern __shared__ float sm[];
    float* Qs = sm;                         // [128][FS]
    float* Ks = sm + 128 * FS;              // [64][FS]
    float* Ss = sm + 192 * FS;              // [128][FS]
    float* Vs = sm + 320 * FS;              // [64][VS]

    const int tid  = threadIdx.x;
    const int lane = tid & 31;
    const int warp = tid >> 5;      // 0..3 -> rows 32*warp..32*warp+31
    const int grp  = lane >> 2;
    const int tig  = lane & 3;

    const int rA0 = warp * 32 + grp;        // m-group 0 row base
    const int rB0 = warp * 32 + 16 + grp;   // m-group 1 row base

    const int part  = lane >> 3;
    const int rselA = (lane & 7) + ((part & 1) << 3);   // A-side
    const int coffA = (part >> 1) << 4;
    const int rselB = (lane & 7) + ((part >> 1) << 3);  // B-side
    const int coffB = (part & 1) << 4;

    const uint32_t qs_u32 = (uint32_t)__cvta_generic_to_shared(Qs);
    const uint32_t ks_u32 = (uint32_t)__cvta_generic_to_shared(Ks);
    const uint32_t ss_u32 = (uint32_t)__cvta_generic_to_shared(Ss);
    const uint32_t qA_lm = qs_u32 + (uint32_t)((warp * 32 + rselA) * FS) * 4u + coffA;
    const uint32_t qB_lm = qA_lm + (uint32_t)(16 * FS) * 4u;
    const uint32_t sA_lm = ss_u32 + (uint32_t)((warp * 32 + rselA) * FS) * 4u + coffA;
    const uint32_t sB_lm = sA_lm + (uint32_t)(16 * FS) * 4u;
    const uint32_t k_lm  = ks_u32 + (uint32_t)(rselB * FS) * 4u + coffB;

    // Load Q tile [128][64], scale, tf32-convert
    for (int idx = tid; idx < 128 * 16; idx += 128) {
        const int r  = idx >> 4;
        const int c4 = (idx & 15) << 2;
        const size_t g = (size_t)(b * TT + qbase + r) * NQKV + h * DD + c4;
        float4 v = *(const float4*)&qkv[g];
        v.x = to_tf32(v.x * QSCALE); v.y = to_tf32(v.y * QSCALE);
        v.z = to_tf32(v.z * QSCALE); v.w = to_tf32(v.w * QSCALE);
        *(float4*)&Qs[r * FS + c4] = v;
    }

    float o[2][8][4];
    #pragma unroll
    for (int gq = 0; gq < 2; gq++)
        #pragma unroll
        for (int i = 0; i < 8; i++)
            #pragma unroll
            for (int j = 0; j < 4; j++)
                o[gq][i][j] = 0.0f;

    float mA0 = -1e30f, mA1 = -1e30f, mB0 = -1e30f, mB1 = -1e30f;
    float lA0 = 0.0f,   lA1 = 0.0f,   lB0 = 0.0f,   lB1 = 0.0f;

    const int nkt = 2 * qi + 2;
    for (int kt = 0; kt < nkt; kt++) {
        // Load K/V tiles [64][64], tf32-convert
        for (int idx = tid; idx < 64 * 16; idx += 128) {
            const int r  = idx >> 4;
            const int c4 = (idx & 15) << 2;
            const size_t g = (size_t)(b * TT + kt * 64 + r) * NQKV + h * DD + c4;
            float4 kv = *(const float4*)&qkv[g + CC];
            float4 vv = *(const float4*)&qkv[g + 2 * CC];
            kv.x = to_tf32(kv.x); kv.y = to_tf32(kv.y);
            kv.z = to_tf32(kv.z); kv.w = to_tf32(kv.w);
            vv.x = to_tf32(vv.x); vv.y = to_tf32(vv.y);
            vv.z = to_tf32(vv.z); vv.w = to_tf32(vv.w);
            *(float4*)&Ks[r * FS + c4] = kv;
            *(float4*)&Vs[r * VS + c4] = vv;
        }
        __syncthreads();

        // S = Q K^T for both m-groups; K fragments loaded once
        float sf[2][8][4];
        #pragma unroll
        for (int gq = 0; gq < 2; gq++)
            #pragma unroll
            for (int na = 0; na < 8; na++)
                #pragma unroll
                for (int j = 0; j < 4; j++)
                    sf[gq][na][j] = 0.0f;

        #pragma unroll
        for (int ka = 0; ka < 8; ka++) {
            uint32_t qfA[4], qfB[4];
            ldsm_x4(qfA[0], qfA[1], qfA[2], qfA[3], qA_lm + (uint32_t)(ka * 32));
            ldsm_x4(qfB[0], qfB[1], qfB[2], qfB[3], qB_lm + (uint32_t)(ka * 32));
            uint32_t kf[8][2];
            #pragma unroll
            for (int p = 0; p < 4; p++)
                ldsm_x4(kf[2 * p][0], kf[2 * p][1], kf[2 * p + 1][0], kf[2 * p + 1][1],
                        k_lm + (uint32_t)(p * 16 * FS) * 4u + (uint32_t)(ka * 32));
            #pragma unroll
            for (int na = 0; na < 8; na++) {
                mma_tf32_u(sf[0][na], qfA, kf[na]);
                mma_tf32_u(sf[1][na], qfB, kf[na]);
            }
        }

        // Causal mask (only on the last two k-tiles)
        if (kt >= 2 * qi) {
            #pragma unroll
            for (int na = 0; na < 8; na++) {
                const int c = kt * 64 + na * 8 + 2 * tig;
                const int gA0 = qbase + rA0, gB0 = qbase + rB0;
                if (c     > gA0)     sf[0][na][0] = -1e30f;
                if (c + 1 > gA0)     sf[0][na][1] = -1e30f;
                if (c     > gA0 + 8) sf[0][na][2] = -1e30f;
                if (c + 1 > gA0 + 8) sf[0][na][3] = -1e30f;
                if (c     > gB0)     sf[1][na][0] = -1e30f;
                if (c + 1 > gB0)     sf[1][na][1] = -1e30f;
                if (c     > gB0 + 8) sf[1][na][2] = -1e30f;
                if (c + 1 > gB0 + 8) sf[1][na][3] = -1e30f;
            }
        }

        // Register online softmax for 4 row-sets (A0,A1,B0,B1)
        float mx[4] = {-1e30f, -1e30f, -1e30f, -1e30f};
        #pragma unroll
        for (int na = 0; na < 8; na++) {
            mx[0] = fmaxf(mx[0], fmaxf(sf[0][na][0], sf[0][na][1]));
            mx[1] = fmaxf(mx[1], fmaxf(sf[0][na][2], sf[0][na][3]));
            mx[2] = fmaxf(mx[2], fmaxf(sf[1][na][0], sf[1][na][1]));
            mx[3] = fmaxf(mx[3], fmaxf(sf[1][na][2], sf[1][na][3]));
        }
        #pragma unroll
        for (int q4 = 0; q4 < 4; q4++) {
            mx[q4] = fmaxf(mx[q4], __shfl_xor_sync(0xFFFFFFFFu, mx[q4], 1));
            mx[q4] = fmaxf(mx[q4], __shfl_xor_sync(0xFFFFFFFFu, mx[q4], 2));
        }

        const float nmA0 = fmaxf(mA0, mx[0]);
        const float nmA1 = fmaxf(mA1, mx[1]);
        const float nmB0 = fmaxf(mB0, mx[2]);
        const float nmB1 = fmaxf(mB1, mx[3]);
        const float scA0 = ex2(mA0 - nmA0);
        const float scA1 = ex2(mA1 - nmA1);
        const float scB0 = ex2(mB0 - nmB0);
        const float scB1 = ex2(mB1 - nmB1);
        mA0 = nmA0; mA1 = nmA1; mB0 = nmB0; mB1 = nmB1;

        float s0 = 0.f, s1 = 0.f, s2 = 0.f, s3 = 0.f;
        #pragma unroll
        for (int na = 0; na < 8; na++) {
            const float pA0 = ex2(sf[0][na][0] - nmA0);
            const float pA1 = ex2(sf[0][na][1] - nmA0);
            const float pA2 = ex2(sf[0][na][2] - nmA1);
            const float pA3 = ex2(sf[0][na][3] - nmA1);
            const float pB0 = ex2(sf[1][na][0] - nmB0);
            const float pB1 = ex2(sf[1][na][1] - nmB0);
            const float pB2 = ex2(sf[1][na][2] - nmB1);
            const float pB3 = ex2(sf[1][na][3] - nmB1);
            s0 += pA0 + pA1;  s1 += pA2 + pA3;
            s2 += pB0 + pB1;  s3 += pB2 + pB3;
            float2 w;
            w.x = to_tf32(pA0); w.y = to_tf32(pA1);
            *(float2*)&Ss[rA0 * FS + na * 8 + 2 * tig] = w;
            w.x = to_tf32(pA2); w.y = to_tf32(pA3);
            *(float2*)&Ss[(rA0 + 8) * FS + na * 8 + 2 * tig] = w;
            w.x = to_tf32(pB0); w.y = to_tf32(pB1);
            *(float2*)&Ss[rB0 * FS + na * 8 + 2 * tig] = w;
            w.x = to_tf32(pB2); w.y = to_tf32(pB3);
            *(float2*)&Ss[(rB0 + 8) * FS + na * 8 + 2 * tig] = w;
            o[0][na][0] *= scA0; o[0][na][1] *= scA0;
            o[0][na][2] *= scA1; o[0][na][3] *= scA1;
            o[1][na][0] *= scB0; o[1][na][1] *= scB0;
            o[1][na][2] *= scB1; o[1][na][3] *= scB1;
        }
        s0 += __shfl_xor_sync(0xFFFFFFFFu, s0, 1);
        s0 += __shfl_xor_sync(0xFFFFFFFFu, s0, 2);
        s1 += __shfl_xor_sync(0xFFFFFFFFu, s1, 1);
        s1 += __shfl_xor_sync(0xFFFFFFFFu, s1, 2);
        s2 += __shfl_xor_sync(0xFFFFFFFFu, s2, 1);
        s2 += __shfl_xor_sync(0xFFFFFFFFu, s2, 2);
        s3 += __shfl_xor_sync(0xFFFFFFFFu, s3, 1);
        s3 += __shfl_xor_sync(0xFFFFFFFFu, s3, 2);
        lA0 = lA0 * scA0 + s0;
        lA1 = lA1 * scA1 + s1;
        lB0 = lB0 * scB0 + s2;
        lB1 = lB1 * scB1 + s3;

        __syncwarp();   // S rows are warp-private

        // O += P @ V ; V fragments loaded once, shared by both m-groups
        #pragma unroll
        for (int ka = 0; ka < 8; ka++) {
            const int kb = ka * 8;
            uint32_t pfA[4], pfB[4];
            ldsm_x4(pfA[0], pfA[1], pfA[2], pfA[3], sA_lm + (uint32_t)(ka * 32));
            ldsm_x4(pfB[0], pfB[1], pfB[2], pfB[3], sB_lm + (uint32_t)(ka * 32));
            #pragma unroll
            for (int na = 0; na < 8; na++) {
                uint32_t vf[2];
                vf[0] = __float_as_uint(Vs[(kb + tig) * VS + na * 8 + grp]);
                vf[1] = __float_as_uint(Vs[(kb + tig + 4) * VS + na * 8 + grp]);
                mma_tf32_u(o[0][na], pfA, vf);
                mma_tf32_u(o[1][na], pfB, vf);
            }
        }
        __syncthreads();
    }

    // Final normalize + store
    const float invA0 = 1.0f / lA0;
    const float invA1 = 1.0f / lA1;
    const float invB0 = 1.0f / lB0;
    const float invB1 = 1.0f / lB1;
    const size_t baseA0 = (size_t)(b * TT + qbase + rA0) * CC + h * DD;
    const size_t baseA1 = (size_t)(b * TT + qbase + rA0 + 8) * CC + h * DD;
    const size_t baseB0 = (size_t)(b * TT + qbase + rB0) * CC + h * DD;
    const size_t baseB1 = (size_t)(b * TT + qbase + rB0 + 8) * CC + h * DD;
    #pragma unroll
    for (int na = 0; na < 8; na++) {
        const int c = na * 8 + 2 * tig;
        float2 w;
        w.x = o[0][na][0] * invA0; w.y = o[0][na][1] * invA0;
        *(float2*)&out[baseA0 + c] = w;
        w.x = o[0][na][2] * invA1; w.y = o[0][na][3] * invA1;
        *(float2*)&out[baseA1 + c] = w;
        w.x = o[1][na][0] * invB0; w.y = o[1][na][1] * invB0;
        *(float2*)&out[baseB0 + c] = w;
        w.x = o[1][na][2] * invB1; w.y = o[1][na][3] * invB1;
        *(float2*)&out[baseB1 + c] = w;
    }
}

// ---------------------------------------------------------------------------
// Launch
// ---------------------------------------------------------------------------
extern "C" void kernel_launch(void* const* d_in, const int* in_sizes, int n_in,
                              void* d_out, int out_size)
{
    const float* x      = (const float*)d_in[0];
    const float* W_attn = (const float*)d_in[1];
    const float* b_attn = (const float*)d_in[2];
    const float* W_proj = (const float*)d_in[3];
    const float* b_proj = (const float*)d_in[4];
    float* out = (float*)d_out;

    float* qkv = nullptr;
    float* att = nullptr;
    cudaGetSymbolAddress((void**)&qkv, g_qkv);
    cudaGetSymbolAddress((void**)&att, g_att);
    cudaFuncSetAttribute(attn_tf32_kernel,
                         cudaFuncAttributeMaxDynamicSharedMemorySize, ATTN_SMEM);

    gemm_tf32_kernel<<<dim3(NQKV / 128, MTOK / 128), 256>>>(x, W_attn, b_attn, qkv, NQKV);
    attn_tf32_kernel<<<dim3(TT / 128, HH, BBATCH), 128, ATTN_SMEM>>>(qkv, att);
    gemm_tf32_kernel<<<dim3(CC / 128, MTOK / 128), 256>>>(att, W_proj, b_proj, out, CC);
}

// round 15
// speedup vs baseline: 3.4483x; 1.0144x over previous
#include <cuda_runtime.h>
#include <cstdint>

// Problem constants
#define TT   2048
#define CC   768
#define NQKV 2304
#define HH   12
#define DD   64
#define BBATCH 2
#define MTOK 4096   // B*T

// Scratch (allocation-free rule: __device__ globals)
__device__ float g_qkv[MTOK * NQKV];   // [4096, 2304]
__device__ float g_att[MTOK * CC];     // [4096, 768]
// Split-K attention partials: 192 split-tiles x 2 halves
__device__ float g_po[192 * 2 * 128 * 64];   // unnormalized O
__device__ float g_pm[192 * 2 * 128];        // row max (log2 domain)
__device__ float g_pl[192 * 2 * 128];        // row sum
__device__ int   g_flag[192];                // arrival flags (zero-init; combiner resets)

// ---------------------------------------------------------------------------
// Helpers
// ---------------------------------------------------------------------------
__device__ __forceinline__ float to_tf32(float x) {
    float y;
    asm("cvt.rna.tf32.f32 %0, %1;" : "=f"(y) : "f"(x));
    return y;
}

__device__ __forceinline__ float ex2(float x) {
    float y;
    asm("ex2.approx.f32 %0, %1;" : "=f"(y) : "f"(x));
    return y;
}

__device__ __forceinline__ void ldsm_x4(uint32_t& r0, uint32_t& r1,
                                        uint32_t& r2, uint32_t& r3, uint32_t addr) {
    asm volatile("ldmatrix.sync.aligned.m8n8.x4.shared.b16 {%0,%1,%2,%3}, [%4];"
                 : "=r"(r0), "=r"(r1), "=r"(r2), "=r"(r3) : "r"(addr));
}

__device__ __forceinline__ void mma_tf32_u(float* d, const uint32_t* a, const uint32_t* b) {
    asm volatile(
        "mma.sync.aligned.m16n8k8.row.col.f32.tf32.tf32.f32 "
        "{%0,%1,%2,%3}, {%4,%5,%6,%7}, {%8,%9}, {%0,%1,%2,%3};\n"
        : "+f"(d[0]), "+f"(d[1]), "+f"(d[2]), "+f"(d[3])
        : "r"(a[0]), "r"(a[1]), "r"(a[2]), "r"(a[3]), "r"(b[0]), "r"(b[1]));
}

// ---------------------------------------------------------------------------
// TF32 GEMM + bias (EXACT R9/R12 version, measured 100.3-100.7us; tf32 HMMA
// ceiling at ~48% tensor; tcgen05 rejected by this toolchain's ptx target)
// ---------------------------------------------------------------------------
#define GAS 36
#define GBS 136

__global__ __launch_bounds__(256) void gemm_tf32_kernel(
    const float* __restrict__ A, const float* __restrict__ B,
    const float* __restrict__ bias, float* __restrict__ C, int N)
{
    __shared__ float As[128 * GAS];
    __shared__ float Bs[32 * GBS];

    const int tid  = threadIdx.x;
    const int lane = tid & 31;
    const int warp = tid >> 5;
    const int wm   = warp >> 2;
    const int wn   = warp & 3;
    const int grp  = lane >> 2;
    const int tig  = lane & 3;
    const int bx   = blockIdx.x;
    const int by   = blockIdx.y;

    const int part = lane >> 3;
    const int rsel = (lane & 7) + ((part & 1) << 3);
    const int coff = (part >> 1) << 4;
    const uint32_t as_u32 = (uint32_t)__cvta_generic_to_shared(As);
    const uint32_t a_lm   = as_u32 + (uint32_t)((wm * 64 + rsel) * GAS) * 4u + coff;

    const int a_row  = tid >> 3;
    const int a_col4 = (tid & 7) << 2;
    const int b_krow = tid >> 5;
    const int b_col4 = (tid & 31) << 2;

    const int cbase = wn * 32 + grp;

    float acc[4][4][4];
    #pragma unroll
    for (int i = 0; i < 4; i++)
        #pragma unroll
        for (int j = 0; j < 4; j++)
            #pragma unroll
            for (int k = 0; k < 4; k++)
                acc[i][j][k] = 0.0f;

    for (int k0 = 0; k0 < 768; k0 += 32) {
        #pragma unroll
        for (int i = 0; i < 4; i++) {
            const int r = a_row + 32 * i;
            float4 v = *(const float4*)&A[(size_t)(by * 128 + r) * 768 + k0 + a_col4];
            v.x = to_tf32(v.x); v.y = to_tf32(v.y);
            v.z = to_tf32(v.z); v.w = to_tf32(v.w);
            *(float4*)&As[r * GAS + a_col4] = v;
        }
        #pragma unroll
        for (int i = 0; i < 4; i++) {
            const int kr = b_krow + 8 * i;
            float4 v = *(const float4*)&B[(size_t)(k0 + kr) * N + bx * 128 + b_col4];
            v.x = to_tf32(v.x); v.y = to_tf32(v.y);
            v.z = to_tf32(v.z); v.w = to_tf32(v.w);
            *(float4*)&Bs[kr * GBS + b_col4] = v;
        }
        __syncthreads();

        #pragma unroll
        for (int ka = 0; ka < 4; ka++) {
            const int kb = ka * 8;
            uint32_t af[4][4];
            #pragma unroll
            for (int ma = 0; ma < 4; ma++)
                ldsm_x4(af[ma][0], af[ma][1], af[ma][2], af[ma][3],
                        a_lm + (uint32_t)(ma * 16 * GAS) * 4u + (uint32_t)(ka * 32));
            uint32_t bf[4][2];
            #pragma unroll
            for (int na = 0; na < 4; na++) {
                bf[na][0] = __float_as_uint(Bs[(kb + tig) * GBS + cbase + na * 8]);
                bf[na][1] = __float_as_uint(Bs[(kb + tig + 4) * GBS + cbase + na * 8]);
            }
            #pragma unroll
            for (int ma = 0; ma < 4; ma++)
                #pragma unroll
                for (int na = 0; na < 4; na++)
                    mma_tf32_u(acc[ma][na], af[ma], bf[na]);
        }
        __syncthreads();
    }

    #pragma unroll
    for (int ma = 0; ma < 4; ma++) {
        const int row = by * 128 + wm * 64 + ma * 16 + grp;
        #pragma unroll
        for (int na = 0; na < 4; na++) {
            const int col = bx * 128 + wn * 32 + na * 8 + 2 * tig;
            const float2 bv = *(const float2*)&bias[col];
            float2 r0v, r1v;
            r0v.x = acc[ma][na][0] + bv.x;
            r0v.y = acc[ma][na][1] + bv.y;
            r1v.x = acc[ma][na][2] + bv.x;
            r1v.y = acc[ma][na][3] + bv.y;
            *(float2*)&C[(size_t)row * N + col]       = r0v;
            *(float2*)&C[(size_t)(row + 8) * N + col] = r1v;
        }
    }
}

// ---------------------------------------------------------------------------
// Flash-attention, TF32 (R12 core: 4 warps x 32 q-rows, ldmatrix Q/K/S,
// conflict-free V, exp2 softmax, register state).
// Split-K load balancing: per (h,b): bx 0..15 = split halves of q-tiles
// 8..15 (key range halved); bx 16..23 = unsplit q-tiles 7..0. Max block
// work 16 k-tiles (was 32). Split blocks publish partials; second-arriving
// block combines (symmetric merge -> deterministic).
// ---------------------------------------------------------------------------
#define FS 68
#define VS 72
#define ATTN_SMEM (((128 + 64 + 128) * FS + 64 * VS) * (int)sizeof(float))
#define QSCALE 0.18033688f   // 0.125 * log2(e)

__global__ __launch_bounds__(128, 2) void attn_tf32_kernel(
    const float* __restrict__ qkv, float* __restrict__ out)
{
    const int bx = blockIdx.x;   // 0..23
    const int h  = blockIdx.y;
    const int b  = blockIdx.z;

    int qi, kt0, kt1, sid = -1, half = 0;
    if (bx < 16) {
        qi   = 15 - (bx >> 1);          // 15..8, heavy first
        half = bx & 1;
        const int nk = 2 * qi + 2;
        kt0 = half ? (nk >> 1) : 0;
        kt1 = half ? nk : (nk >> 1);
        sid = (b * HH + h) * 8 + (qi - 8);
    } else {
        qi  = 23 - bx;                  // 7..0
        kt0 = 0;
        kt1 = 2 * qi + 2;
    }
    const int qbase = qi * 128;

    extern __shared__ float sm[];
    float* Qs = sm;                         // [128][FS]
    float* Ks = sm + 128 * FS;              // [64][FS]
    float* Ss = sm + 192 * FS;              // [128][FS]
    float* Vs = sm + 320 * FS;              // [64][VS]

    const int tid  = threadIdx.x;
    const int lane = tid & 31;
    const int warp = tid >> 5;
    const int grp  = lane >> 2;
    const int tig  = lane & 3;

    const int rA0 = warp * 32 + grp;
    const int rB0 = warp * 32 + 16 + grp;

    const int part  = lane >> 3;
    const int rselA = (lane & 7) + ((part & 1) << 3);
    const int coffA = (part >> 1) << 4;
    const int rselB = (lane & 7) + ((part >> 1) << 3);
    const int coffB = (part & 1) << 4;

    const uint32_t qs_u32 = (uint32_t)__cvta_generic_to_shared(Qs);
    const uint32_t ks_u32 = (uint32_t)__cvta_generic_to_shared(Ks);
    const uint32_t ss_u32 = (uint32_t)__cvta_generic_to_shared(Ss);
    const uint32_t qA_lm = qs_u32 + (uint32_t)((warp * 32 + rselA) * FS) * 4u + coffA;
    const uint32_t qB_lm = qA_lm + (uint32_t)(16 * FS) * 4u;
    const uint32_t sA_lm = ss_u32 + (uint32_t)((warp * 32 + rselA) * FS) * 4u + coffA;
    const uint32_t sB_lm = sA_lm + (uint32_t)(16 * FS) * 4u;
    const uint32_t k_lm  = ks_u32 + (uint32_t)(rselB * FS) * 4u + coffB;

    // Load Q tile [128][64], scale, tf32-convert
    for (int idx = tid; idx < 128 * 16; idx += 128) {
        const int r  = idx >> 4;
        const int c4 = (idx & 15) << 2;
        const size_t g = (size_t)(b * TT + qbase + r) * NQKV + h * DD + c4;
        float4 v = *(const float4*)&qkv[g];
        v.x = to_tf32(v.x * QSCALE); v.y = to_tf32(v.y * QSCALE);
        v.z = to_tf32(v.z * QSCALE); v.w = to_tf32(v.w * QSCALE);
        *(float4*)&Qs[r * FS + c4] = v;
    }

    float o[2][8][4];
    #pragma unroll
    for (int gq = 0; gq < 2; gq++)
        #pragma unroll
        for (int i = 0; i < 8; i++)
            #pragma unroll
            for (int j = 0; j < 4; j++)
                o[gq][i][j] = 0.0f;

    float mA0 = -1e30f, mA1 = -1e30f, mB0 = -1e30f, mB1 = -1e30f;
    float lA0 = 0.0f,   lA1 = 0.0f,   lB0 = 0.0f,   lB1 = 0.0f;

    for (int kt = kt0; kt < kt1; kt++) {
        // Load K/V tiles [64][64], tf32-convert
        for (int idx = tid; idx < 64 * 16; idx += 128) {
            const int r  = idx >> 4;
            const int c4 = (idx & 15) << 2;
            const size_t g = (size_t)(b * TT + kt * 64 + r) * NQKV + h * DD + c4;
            float4 kv = *(const float4*)&qkv[g + CC];
            float4 vv = *(const float4*)&qkv[g + 2 * CC];
            kv.x = to_tf32(kv.x); kv.y = to_tf32(kv.y);
            kv.z = to_tf32(kv.z); kv.w = to_tf32(kv.w);
            vv.x = to_tf32(vv.x); vv.y = to_tf32(vv.y);
            vv.z = to_tf32(vv.z); vv.w = to_tf32(vv.w);
            *(float4*)&Ks[r * FS + c4] = kv;
            *(float4*)&Vs[r * VS + c4] = vv;
        }
        __syncthreads();

        // S = Q K^T for both m-groups; K fragments loaded once
        float sf[2][8][4];
        #pragma unroll
        for (int gq = 0; gq < 2; gq++)
            #pragma unroll
            for (int na = 0; na < 8; na++)
                #pragma unroll
                for (int j = 0; j < 4; j++)
                    sf[gq][na][j] = 0.0f;

        #pragma unroll
        for (int ka = 0; ka < 8; ka++) {
            uint32_t qfA[4], qfB[4];
            ldsm_x4(qfA[0], qfA[1], qfA[2], qfA[3], qA_lm + (uint32_t)(ka * 32));
            ldsm_x4(qfB[0], qfB[1], qfB[2], qfB[3], qB_lm + (uint32_t)(ka * 32));
            uint32_t kf[8][2];
            #pragma unroll
            for (int p = 0; p < 4; p++)
                ldsm_x4(kf[2 * p][0], kf[2 * p][1], kf[2 * p + 1][0], kf[2 * p + 1][1],
                        k_lm + (uint32_t)(p * 16 * FS) * 4u + (uint32_t)(ka * 32));
            #pragma unroll
            for (int na = 0; na < 8; na++) {
                mma_tf32_u(sf[0][na], qfA, kf[na]);
                mma_tf32_u(sf[1][na], qfB, kf[na]);
            }
        }

        // Causal mask (only on the last two k-tiles of the full range)
        if (kt >= 2 * qi) {
            #pragma unroll
            for (int na = 0; na < 8; na++) {
                const int c = kt * 64 + na * 8 + 2 * tig;
                const int gA0 = qbase + rA0, gB0 = qbase + rB0;
                if (c     > gA0)     sf[0][na][0] = -1e30f;
                if (c + 1 > gA0)     sf[0][na][1] = -1e30f;
                if (c     > gA0 + 8) sf[0][na][2] = -1e30f;
                if (c + 1 > gA0 + 8) sf[0][na][3] = -1e30f;
                if (c     > gB0)     sf[1][na][0] = -1e30f;
                if (c + 1 > gB0)     sf[1][na][1] = -1e30f;
                if (c     > gB0 + 8) sf[1][na][2] = -1e30f;
                if (c + 1 > gB0 + 8) sf[1][na][3] = -1e30f;
            }
        }

        // Register online softmax for 4 row-sets
        float mx[4] = {-1e30f, -1e30f, -1e30f, -1e30f};
        #pragma unroll
        for (int na = 0; na < 8; na++) {
            mx[0] = fmaxf(mx[0], fmaxf(sf[0][na][0], sf[0][na][1]));
            mx[1] = fmaxf(mx[1], fmaxf(sf[0][na][2], sf[0][na][3]));
            mx[2] = fmaxf(mx[2], fmaxf(sf[1][na][0], sf[1][na][1]));
            mx[3] = fmaxf(mx[3], fmaxf(sf[1][na][2], sf[1][na][3]));
        }
        #pragma unroll
        for (int q4 = 0; q4 < 4; q4++) {
            mx[q4] = fmaxf(mx[q4], __shfl_xor_sync(0xFFFFFFFFu, mx[q4], 1));
            mx[q4] = fmaxf(mx[q4], __shfl_xor_sync(0xFFFFFFFFu, mx[q4], 2));
        }

        const float nmA0 = fmaxf(mA0, mx[0]);
        const float nmA1 = fmaxf(mA1, mx[1]);
        const float nmB0 = fmaxf(mB0, mx[2]);
        const float nmB1 = fmaxf(mB1, mx[3]);
        const float scA0 = ex2(mA0 - nmA0);
        const float scA1 = ex2(mA1 - nmA1);
        const float scB0 = ex2(mB0 - nmB0);
        const float scB1 = ex2(mB1 - nmB1);
        mA0 = nmA0; mA1 = nmA1; mB0 = nmB0; mB1 = nmB1;

        float s0 = 0.f, s1 = 0.f, s2 = 0.f, s3 = 0.f;
        #pragma unroll
        for (int na = 0; na < 8; na++) {
            const float pA0 = ex2(sf[0][na][0] - nmA0);
            const float pA1 = ex2(sf[0][na][1] - nmA0);
            const float pA2 = ex2(sf[0][na][2] - nmA1);
            const float pA3 = ex2(sf[0][na][3] - nmA1);
            const float pB0 = ex2(sf[1][na][0] - nmB0);
            const float pB1 = ex2(sf[1][na][1] - nmB0);
            const float pB2 = ex2(sf[1][na][2] - nmB1);
            const float pB3 = ex2(sf[1][na][3] - nmB1);
            s0 += pA0 + pA1;  s1 += pA2 + pA3;
            s2 += pB0 + pB1;  s3 += pB2 + pB3;
            float2 w;
            w.x = to_tf32(pA0); w.y = to_tf32(pA1);
            *(float2*)&Ss[rA0 * FS + na * 8 + 2 * tig] = w;
            w.x = to_tf32(pA2); w.y = to_tf32(pA3);
            *(float2*)&Ss[(rA0 + 8) * FS + na * 8 + 2 * tig] = w;
            w.x = to_tf32(pB0); w.y = to_tf32(pB1);
            *(float2*)&Ss[rB0 * FS + na * 8 + 2 * tig] = w;
            w.x = to_tf32(pB2); w.y = to_tf32(pB3);
            *(float2*)&Ss[(rB0 + 8) * FS + na * 8 + 2 * tig] = w;
            o[0][na][0] *= scA0; o[0][na][1] *= scA0;
            o[0][na][2] *= scA1; o[0][na][3] *= scA1;
            o[1][na][0] *= scB0; o[1][na][1] *= scB0;
            o[1][na][2] *= scB1; o[1][na][3] *= scB1;
        }
        s0 += __shfl_xor_sync(0xFFFFFFFFu, s0, 1);
        s0 += __shfl_xor_sync(0xFFFFFFFFu, s0, 2);
        s1 += __shfl_xor_sync(0xFFFFFFFFu, s1, 1);
        s1 += __shfl_xor_sync(0xFFFFFFFFu, s1, 2);
        s2 += __shfl_xor_sync(0xFFFFFFFFu, s2, 1);
        s2 += __shfl_xor_sync(0xFFFFFFFFu, s2, 2);
        s3 += __shfl_xor_sync(0xFFFFFFFFu, s3, 1);
        s3 += __shfl_xor_sync(0xFFFFFFFFu, s3, 2);
        lA0 = lA0 * scA0 + s0;
        lA1 = lA1 * scA1 + s1;
        lB0 = lB0 * scB0 + s2;
        lB1 = lB1 * scB1 + s3;

        __syncwarp();

        // O += P @ V
        #pragma unroll
        for (int ka = 0; ka < 8; ka++) {
            const int kb = ka * 8;
            uint32_t pfA[4], pfB[4];
            ldsm_x4(pfA[0], pfA[1], pfA[2], pfA[3], sA_lm + (uint32_t)(ka * 32));
            ldsm_x4(pfB[0], pfB[1], pfB[2], pfB[3], sB_lm + (uint32_t)(ka * 32));
            #pragma unroll
            for (int na = 0; na < 8; na++) {
                uint32_t vf[2];
                vf[0] = __float_as_uint(Vs[(kb + tig) * VS + na * 8 + grp]);
                vf[1] = __float_as_uint(Vs[(kb + tig + 4) * VS + na * 8 + grp]);
                mma_tf32_u(o[0][na], pfA, vf);
                mma_tf32_u(o[1][na], pfB, vf);
            }
        }
        __syncthreads();
    }

    if (sid < 0) {
        // Unsplit: normalize + store directly
        const float invA0 = 1.0f / lA0;
        const float invA1 = 1.0f / lA1;
        const float invB0 = 1.0f / lB0;
        const float invB1 = 1.0f / lB1;
        const size_t baseA0 = (size_t)(b * TT + qbase + rA0) * CC + h * DD;
        const size_t baseA1 = (size_t)(b * TT + qbase + rA0 + 8) * CC + h * DD;
        const size_t baseB0 = (size_t)(b * TT + qbase + rB0) * CC + h * DD;
        const size_t baseB1 = (size_t)(b * TT + qbase + rB0 + 8) * CC + h * DD;
        #pragma unroll
        for (int na = 0; na < 8; na++) {
            const int c = na * 8 + 2 * tig;
            float2 w;
            w.x = o[0][na][0] * invA0; w.y = o[0][na][1] * invA0;
            *(float2*)&out[baseA0 + c] = w;
            w.x = o[0][na][2] * invA1; w.y = o[0][na][3] * invA1;
            *(float2*)&out[baseA1 + c] = w;
            w.x = o[1][na][0] * invB0; w.y = o[1][na][1] * invB0;
            *(float2*)&out[baseB0 + c] = w;
            w.x = o[1][na][2] * invB1; w.y = o[1][na][3] * invB1;
            *(float2*)&out[baseB1 + c] = w;
        }
        return;
    }

    // ---- Split path: publish partial, then second arrival combines ----
    {
        float* po = g_po + (size_t)(sid * 2 + half) * (128 * 64);
        float* pm = g_pm + (sid * 2 + half) * 128;
        float* pl = g_pl + (sid * 2 + half) * 128;

        #pragma unroll
        for (int na = 0; na < 8; na++) {
            const int c = na * 8 + 2 * tig;
            float2 w;
            w.x = o[0][na][0]; w.y = o[0][na][1];
            *(float2*)&po[rA0 * 64 + c] = w;
            w.x = o[0][na][2]; w.y = o[0][na][3];
            *(float2*)&po[(rA0 + 8) * 64 + c] = w;
            w.x = o[1][na][0]; w.y = o[1][na][1];
            *(float2*)&po[rB0 * 64 + c] = w;
            w.x = o[1][na][2]; w.y = o[1][na][3];
            *(float2*)&po[(rB0 + 8) * 64 + c] = w;
        }
        if (tig == 0) {
            pm[rA0] = mA0;     pl[rA0] = lA0;
            pm[rA0 + 8] = mA1; pl[rA0 + 8] = lA1;
            pm[rB0] = mB0;     pl[rB0] = lB0;
            pm[rB0 + 8] = mB1; pl[rB0 + 8] = lB1;
        }
        __threadfence();
        __syncthreads();

        __shared__ int s_comb;
        if (tid == 0) s_comb = atomicAdd(&g_flag[sid], 1);
        __syncthreads();
        if (s_comb == 0) return;     // partner will combine
        __threadfence();             // acquire partner's published data

        const int oh = 1 - half;
        const float* qo = g_po + (size_t)(sid * 2 + oh) * (128 * 64);
        const float* qm = g_pm + (sid * 2 + oh) * 128;
        const float* ql = g_pl + (sid * 2 + oh) * 128;

        // Merge partner into own register state, normalize, store.
        const int   rows[4]  = { rA0, rA0 + 8, rB0, rB0 + 8 };
        const float msf[4]   = { mA0, mA1, mB0, mB1 };
        const float lsf[4]   = { lA0, lA1, lB0, lB1 };
        #pragma unroll
        for (int rs = 0; rs < 4; rs++) {
            const int   r   = rows[rs];
            const float m_p = qm[r];
            const float l_p = ql[r];
            const float mm  = fmaxf(msf[rs], m_p);
            const float ws  = ex2(msf[rs] - mm);
            const float wp  = ex2(m_p - mm);
            const float inv = 1.0f / (lsf[rs] * ws + l_p * wp);
            const size_t base = (size_t)(b * TT + qbase + r) * CC + h * DD;
            #pragma unroll
            for (int na = 0; na < 8; na++) {
                const int c = na * 8 + 2 * tig;
                const int i0 = (rs & 2) >> 1;       // m-group
                const int j0 = (rs & 1) << 1;       // 0 or 2
                float2 w;
                w.x = (o[i0][na][j0]     * ws + qo[r * 64 + c]     * wp) * inv;
                w.y = (o[i0][na][j0 + 1] * ws + qo[r * 64 + c + 1] * wp) * inv;
                *(float2*)&out[base + c] = w;
            }
        }
        __syncthreads();
        if (tid == 0) g_flag[sid] = 0;   // reset for next graph replay
    }
}

// ---------------------------------------------------------------------------
// Launch
// ---------------------------------------------------------------------------
extern "C" void kernel_launch(void* const* d_in, const int* in_sizes, int n_in,
                              void* d_out, int out_size)
{
    const float* x      = (const float*)d_in[0];
    const float* W_attn = (const float*)d_in[1];
    const float* b_attn = (const float*)d_in[2];
    const float* W_proj = (const float*)d_in[3];
    const float* b_proj = (const float*)d_in[4];
    float* out = (float*)d_out;

    float* qkv = nullptr;
    float* att = nullptr;
    cudaGetSymbolAddress((void**)&qkv, g_qkv);
    cudaGetSymbolAddress((void**)&att, g_att);
    cudaFuncSetAttribute(attn_tf32_kernel,
                         cudaFuncAttributeMaxDynamicSharedMemorySize, ATTN_SMEM);

    gemm_tf32_kernel<<<dim3(NQKV / 128, MTOK / 128), 256>>>(x, W_attn, b_attn, qkv, NQKV);
    attn_tf32_kernel<<<dim3(24, HH, BBATCH), 128, ATTN_SMEM>>>(qkv, att);
    gemm_tf32_kernel<<<dim3(CC / 128, MTOK / 128), 256>>>(att, W_proj, b_proj, out, CC);
}